// round 6
// baseline (speedup 1.0000x reference)
#include <cuda_runtime.h>
#include <cuda_bf16.h>
#include <math.h>
#include <stdint.h>

#define NT 64
#define NQ 256
#define NPK 100000
#define NE 262144
#define NN 16384
#define DS 64
#define DV 32
#define TEH 128
#define FF 160

#define TILE_E 128
#define TILES2 2048          // tiles per scale (NE / 128)
#define BPS 74               // blocks per scale (148 total)
#define HSTR 196             // Hs row stride (floats)
#define ASTR 37              // A row stride (32-bit words; 74 bf16)

// smem byte offsets
#define OFF_BF   0           // B fragments: 192 frags x 32 lanes x 8 B = 49152
#define OFF_AHI  49152       // 128 x 37 words = 18944
#define OFF_ALO  68096       // 18944
#define OFF_HS   87040       // 128 x 196 floats = 100352
#define OFF_RBS  187392      // 128 x 9 floats = 4608
#define OFF_DIRS 192000      // 1536
#define OFF_INVS 193536      // 512
#define OFF_SRCS 194048      // 512
#define OFF_DSTS 194560      // 512
#define OFF_TTS  195072      // 512
#define OFF_W1S  195584      // 2048
#define OFF_B2S  197632      // 768
#define EDGE_SMEM 198400

__device__ float g_kfeat[NN * FF];
__device__ int   g_cnt[2 * NN];
__device__ int   g_cur[2 * NN];
__device__ float g_invcnt[2 * NN];
__device__ float g_qx[NN * 3];
__device__ float g_R[NT * 9];
__device__ float g_pre[2 * NT * 64];
__device__ int2  g_srt[2 * NE];

__device__ __forceinline__ unsigned short bfbits(float v) {
    __nv_bfloat16 b = __float2bfloat16_rn(v);
    return *reinterpret_cast<unsigned short*>(&b);
}
__device__ __forceinline__ float bf2f(unsigned short u) {
    __nv_bfloat16 b = *reinterpret_cast<__nv_bfloat16*>(&u);
    return __bfloat162float(b);
}

#define MMA_BF16(c, a, b) \
    asm volatile("mma.sync.aligned.m16n8k16.row.col.f32.bf16.bf16.f32 " \
        "{%0,%1,%2,%3}, {%4,%5,%6,%7}, {%8,%9}, {%0,%1,%2,%3};" \
        : "+f"((c)[0]), "+f"((c)[1]), "+f"((c)[2]), "+f"((c)[3]) \
        : "r"((a)[0]), "r"((a)[1]), "r"((a)[2]), "r"((a)[3]), \
          "r"((b)[0]), "r"((b)[1]))

// ---------------- small kernels ----------------
__global__ void zero_kernel(float* __restrict__ out) {
    int i = blockIdx.x * blockDim.x + threadIdx.x;
    int st = gridDim.x * blockDim.x;
    for (int z = i; z < NN * FF; z += st) g_kfeat[z] = 0.0f;
    for (int z = i; z < 2 * NN; z += st) g_cnt[z] = 0;
    if (i < 2 * NT * 3) out[i] = 0.0f;
}

__global__ void hist_kernel(const int* __restrict__ ed0, const int* __restrict__ ed1) {
    int i = blockIdx.x * blockDim.x + threadIdx.x;
    int st = gridDim.x * blockDim.x;
    for (int e = i; e < NE; e += st) atomicAdd(&g_cnt[ed0[e]], 1);
    for (int e = i; e < NE; e += st) atomicAdd(&g_cnt[NN + ed1[e]], 1);
}

__global__ void scan_kernel() {
    __shared__ int sm[1024];
    int tid = threadIdx.x;
    int base = tid * 32;
    int loc[32];
    int s = 0;
    #pragma unroll
    for (int i = 0; i < 32; i++) { loc[i] = g_cnt[base + i]; s += loc[i]; }
    sm[tid] = s;
    __syncthreads();
    for (int off = 1; off < 1024; off <<= 1) {
        int v = (tid >= off) ? sm[tid - off] : 0;
        __syncthreads();
        sm[tid] += v;
        __syncthreads();
    }
    int ex = sm[tid] - s;
    #pragma unroll
    for (int i = 0; i < 32; i++) { g_cur[base + i] = ex; ex += loc[i]; }
}

__global__ void scatter_kernel(const int* __restrict__ es0, const int* __restrict__ ed0,
                               const int* __restrict__ es1, const int* __restrict__ ed1) {
    int i = blockIdx.x * blockDim.x + threadIdx.x;
    int st = gridDim.x * blockDim.x;
    for (int e = i; e < NE; e += st) {
        int d = ed0[e];
        int pos = atomicAdd(&g_cur[d], 1);
        g_srt[pos] = make_int2(es0[e], d);
    }
    for (int e = i; e < NE; e += st) {
        int d = ed1[e];
        int pos = atomicAdd(&g_cur[NN + d], 1);
        g_srt[pos] = make_int2(es1[e], d);
    }
}

__global__ void prep_kernel(const float* __restrict__ Ts, const float* __restrict__ time_,
                            const float* __restrict__ query_x,
                            const float* __restrict__ W_qt, const float* __restrict__ b_qt,
                            const float* __restrict__ W1_r, const float* __restrict__ b1_r) {
    __shared__ float te[128];
    __shared__ float qemb[128];
    __shared__ float Rsh[9];
    __shared__ float tsh[3];
    int t = blockIdx.x;
    int tid = threadIdx.x;  // 128 threads
    float tv = time_[t];
    {
        int k = tid & 63;
        float f = __expf(-logf(10000.0f) * (float)k / 63.0f);
        float a = tv * f;
        te[tid] = (tid < 64) ? sinf(a) : cosf(a);
    }
    if (tid == 0) {
        float qw = Ts[t * 7 + 0], qa = Ts[t * 7 + 1], qb = Ts[t * 7 + 2], qc = Ts[t * 7 + 3];
        float nrm = rsqrtf(qw * qw + qa * qa + qb * qb + qc * qc);
        qw *= nrm; qa *= nrm; qb *= nrm; qc *= nrm;
        Rsh[0] = 1.0f - 2.0f * (qb * qb + qc * qc);
        Rsh[1] = 2.0f * (qa * qb - qw * qc);
        Rsh[2] = 2.0f * (qa * qc + qw * qb);
        Rsh[3] = 2.0f * (qa * qb + qw * qc);
        Rsh[4] = 1.0f - 2.0f * (qa * qa + qc * qc);
        Rsh[5] = 2.0f * (qb * qc - qw * qa);
        Rsh[6] = 2.0f * (qa * qc - qw * qb);
        Rsh[7] = 2.0f * (qb * qc + qw * qa);
        Rsh[8] = 1.0f - 2.0f * (qa * qa + qb * qb);
        tsh[0] = Ts[t * 7 + 4]; tsh[1] = Ts[t * 7 + 5]; tsh[2] = Ts[t * 7 + 6];
        #pragma unroll
        for (int i = 0; i < 9; i++) g_R[t * 9 + i] = Rsh[i];
    }
    __syncthreads();
    {
        int o = tid;
        float acc = b_qt[o];
        for (int k = 0; k < 128; k++) acc += te[k] * W_qt[k * TEH + o];
        qemb[o] = acc;
    }
    __syncthreads();
    {
        int s = tid >> 6, j = tid & 63;
        float acc = b1_r[s * 64 + j];
        const float* w = W1_r + s * 136 * 64 + 8 * 64 + j;
        for (int i = 0; i < 128; i++) acc += qemb[i] * w[i * 64];
        g_pre[(s * NT + t) * 64 + j] = acc;
    }
    for (int q = tid; q < NQ; q += blockDim.x) {
        float x = query_x[q * 3 + 0], y = query_x[q * 3 + 1], z = query_x[q * 3 + 2];
        int n = t * NQ + q;
        g_qx[n * 3 + 0] = Rsh[0] * x + Rsh[1] * y + Rsh[2] * z + tsh[0];
        g_qx[n * 3 + 1] = Rsh[3] * x + Rsh[4] * y + Rsh[5] * z + tsh[1];
        g_qx[n * 3 + 2] = Rsh[6] * x + Rsh[7] * y + Rsh[8] * z + tsh[2];
    }
    int gtid = t * blockDim.x + tid;
    int gst = gridDim.x * blockDim.x;
    for (int z = gtid; z < 2 * NN; z += gst)
        g_invcnt[z] = 1.0f / ((float)g_cnt[z] + 1e-8f);
}

// ---------------- fused edge kernel: mma.sync bf16x3 ----------------
// 148 persistent blocks; even blocks scale 0, odd scale 1; 128-edge tiles.
// H[128x192] = silu(layer1)[128x64] @ W2[64x192] via m16n8k16 bf16 mma,
// 2-split/3-product for fp32-grade accuracy. W2 pre-packed into B-fragment
// layout once per CTA. Epilogue: full-H smem slab -> run-merged atomic scatter.
__global__ __launch_bounds__(256, 1)
void edge_mma_kernel(
    const float* __restrict__ kx0, const float* __restrict__ kf0,
    const float* __restrict__ kx1, const float* __restrict__ kf1,
    const float* __restrict__ W1_r, const float* __restrict__ W2_r,
    const float* __restrict__ b2_r) {
    extern __shared__ char smem[];
    int tid = threadIdx.x;
    int wid = tid >> 5, lane = tid & 31;
    int quad = lane >> 2, lm4 = lane & 3;
    int s = blockIdx.x & 1;
    int tstart = blockIdx.x >> 1;

    const float* kx = s ? kx1 : kx0;
    const float* kf = s ? kf1 : kf0;
    const float* preS = g_pre + s * NT * 64;
    const float* icS = g_invcnt + s * NN;
    const int2* srtS = g_srt + s * NE;

    uint2*  Bf2  = (uint2*)(smem + OFF_BF);
    uint32_t* Ahw = (uint32_t*)(smem + OFF_AHI);
    uint32_t* Alw = (uint32_t*)(smem + OFF_ALO);
    float* Hs   = (float*)(smem + OFF_HS);
    float* rbs  = (float*)(smem + OFF_RBS);
    float* dirs = (float*)(smem + OFF_DIRS);
    float* invs = (float*)(smem + OFF_INVS);
    int*   srcs = (int*)(smem + OFF_SRCS);
    int*   dsts = (int*)(smem + OFF_DSTS);
    int*   tts  = (int*)(smem + OFF_TTS);
    float* W1s  = (float*)(smem + OFF_W1S);
    float* b2s  = (float*)(smem + OFF_B2S);

    // --- prologue: W1, b2, B-fragment pack (hi/lo bf16) ---
    for (int i = tid; i < 512; i += 256) W1s[i] = W1_r[s * (136 * 64) + i];
    for (int i = tid; i < 192; i += 256) b2s[i] = b2_r[s * 192 + i];
    // fragment id f = (sp*4 + kt)*24 + gn ; entry (f, lane)
    for (int idx = tid; idx < 6144; idx += 256) {
        int l = idx & 31;
        int f = idx >> 5;
        int gn = f % 24;
        int kt = (f / 24) & 3;
        int sp = f / 96;
        int n = gn * 8 + (l >> 2);
        int k0 = kt * 16 + (l & 3) * 2;
        const float* w2 = W2_r + s * 12288;
        float v00 = w2[k0 * 192 + n];
        float v01 = w2[(k0 + 1) * 192 + n];
        float v10 = w2[(k0 + 8) * 192 + n];
        float v11 = w2[(k0 + 9) * 192 + n];
        uint32_t r0, r1;
        if (sp == 0) {
            r0 = (uint32_t)bfbits(v00) | ((uint32_t)bfbits(v01) << 16);
            r1 = (uint32_t)bfbits(v10) | ((uint32_t)bfbits(v11) << 16);
        } else {
            unsigned short h00 = bfbits(v00), h01 = bfbits(v01);
            unsigned short h10 = bfbits(v10), h11 = bfbits(v11);
            r0 = (uint32_t)bfbits(v00 - bf2f(h00)) | ((uint32_t)bfbits(v01 - bf2f(h01)) << 16);
            r1 = (uint32_t)bfbits(v10 - bf2f(h10)) | ((uint32_t)bfbits(v11 - bf2f(h11)) << 16);
        }
        Bf2[f * 32 + l] = make_uint2(r0, r1);
    }
    __syncthreads();

    // per-warp B fragments (3 n-tiles x 4 k-tiles x {hi,lo}), resident in regs
    uint32_t bfr[3][4][2][2];
    #pragma unroll
    for (int nt = 0; nt < 3; nt++)
        #pragma unroll
        for (int kt = 0; kt < 4; kt++)
            #pragma unroll
            for (int sp = 0; sp < 2; sp++) {
                int f = (sp * 4 + kt) * 24 + (wid * 3 + nt);
                uint2 v = Bf2[f * 32 + lane];
                bfr[nt][kt][sp][0] = v.x;
                bfr[nt][kt][sp][1] = v.y;
            }

    for (int tile = tstart; tile < TILES2; tile += BPS) {
        __syncthreads();
        // phase 1: per-edge geometry + rbf (dst-sorted edges)
        if (tid < TILE_E) {
            int2 sd = srtS[tile * TILE_E + tid];
            int src = sd.x, dst = sd.y;
            float rx = kx[src * 3 + 0] - g_qx[dst * 3 + 0];
            float ry = kx[src * 3 + 1] - g_qx[dst * 3 + 1];
            float rz = kx[src * 3 + 2] - g_qx[dst * 3 + 2];
            float r = sqrtf(rx * rx + ry * ry + rz * rz);
            float ir = 1.0f / (r + 1e-8f);
            dirs[tid * 3 + 0] = rx * ir;
            dirs[tid * 3 + 1] = ry * ir;
            dirs[tid * 3 + 2] = rz * ir;
            #pragma unroll
            for (int i = 0; i < 8; i++) {
                float dcl = r - (4.0f / 7.0f) * (float)i;
                rbs[tid * 9 + i] = __expf(-dcl * dcl * 4.0f);
            }
            invs[tid] = icS[dst];
            srcs[tid] = src; dsts[tid] = dst; tts[tid] = dst >> 8;
        }
        __syncthreads();

        // phase 2: layer1 + silu -> bf16 hi/lo into A smem
        {
            int row = (wid & 3) * 32 + lane;
            int jr = (wid >> 2) * 32;
            float rb[8];
            #pragma unroll
            for (int i = 0; i < 8; i++) rb[i] = rbs[row * 9 + i];
            const float* prow = preS + tts[row] * 64;
            uint32_t hw[16], lw[16];
            #pragma unroll
            for (int p = 0; p < 16; p++) {
                float av[2];
                #pragma unroll
                for (int q = 0; q < 2; q++) {
                    int j = jr + p * 2 + q;
                    float h = __ldg(prow + j);
                    #pragma unroll
                    for (int i = 0; i < 8; i++) h += rb[i] * W1s[i * 64 + j];
                    av[q] = h * (1.0f / (1.0f + __expf(-h)));
                }
                unsigned short h0 = bfbits(av[0]), h1 = bfbits(av[1]);
                hw[p] = (uint32_t)h0 | ((uint32_t)h1 << 16);
                lw[p] = (uint32_t)bfbits(av[0] - bf2f(h0)) |
                        ((uint32_t)bfbits(av[1] - bf2f(h1)) << 16);
            }
            uint32_t base = row * ASTR + (jr >> 1);
            #pragma unroll
            for (int p = 0; p < 16; p++) { Ahw[base + p] = hw[p]; Alw[base + p] = lw[p]; }
        }
        __syncthreads();

        // phase 3: GEMM via mma.sync (bf16x3). warp wid: cols [24w, 24w+24), all rows.
        float acc[3][8][4];
        #pragma unroll
        for (int nt = 0; nt < 3; nt++)
            #pragma unroll
            for (int mc = 0; mc < 8; mc++)
                #pragma unroll
                for (int r = 0; r < 4; r++) acc[nt][mc][r] = 0.0f;

        #pragma unroll
        for (int mc = 0; mc < 8; mc++) {
            int r0 = mc * 16 + quad;
            uint32_t ah[4][4], al[4][4];
            #pragma unroll
            for (int kt = 0; kt < 4; kt++) {
                uint32_t b0 = r0 * ASTR + kt * 8 + lm4;
                uint32_t b1 = (r0 + 8) * ASTR + kt * 8 + lm4;
                ah[kt][0] = Ahw[b0];     ah[kt][1] = Ahw[b1];
                ah[kt][2] = Ahw[b0 + 4]; ah[kt][3] = Ahw[b1 + 4];
                al[kt][0] = Alw[b0];     al[kt][1] = Alw[b1];
                al[kt][2] = Alw[b0 + 4]; al[kt][3] = Alw[b1 + 4];
            }
            #pragma unroll
            for (int nt = 0; nt < 3; nt++)
                #pragma unroll
                for (int kt = 0; kt < 4; kt++) {
                    MMA_BF16(acc[nt][mc], ah[kt], bfr[nt][kt][0]);
                    MMA_BF16(acc[nt][mc], al[kt], bfr[nt][kt][0]);
                    MMA_BF16(acc[nt][mc], ah[kt], bfr[nt][kt][1]);
                }
        }

        // phase 4: accumulators (+bias) -> Hs slab
        #pragma unroll
        for (int nt = 0; nt < 3; nt++) {
            int col = wid * 24 + nt * 8 + lm4 * 2;
            float bb0 = b2s[col], bb1 = b2s[col + 1];
            #pragma unroll
            for (int mc = 0; mc < 8; mc++) {
                int row = mc * 16 + quad;
                float2 v0 = make_float2(acc[nt][mc][0] + bb0, acc[nt][mc][1] + bb1);
                float2 v1 = make_float2(acc[nt][mc][2] + bb0, acc[nt][mc][3] + bb1);
                *(float2*)&Hs[row * HSTR + col] = v0;
                *(float2*)&Hs[(row + 8) * HSTR + col] = v1;
            }
        }
        __syncthreads();

        // phase 5: message + run-merged atomic scatter. warp wid: edges [16w, 16w+16)
        {
            int tx = lane;
            float a0 = 0.f, a1 = 0.f, a2 = 0.f, a3 = 0.f, a4 = 0.f;
            float curinv = 0.f;
            int cur = -1;
            #pragma unroll
            for (int e16 = 0; e16 < 16; e16++) {
                int r = wid * 16 + e16;
                float w0 = Hs[r * HSTR + tx];
                float w1 = Hs[r * HSTR + 32 + tx];
                float w2 = Hs[r * HSTR + 64 + tx];
                float w3 = Hs[r * HSTR + 96 + tx];
                float w4 = Hs[r * HSTR + 128 + tx];
                float w5 = Hs[r * HSTR + 160 + tx];
                const float* kfr = kf + (size_t)srcs[r] * FF;
                float ks1 = __ldg(kfr + tx);
                float ks2 = __ldg(kfr + 32 + tx);
                float kvx = __ldg(kfr + 64 + 3 * tx + 0);
                float kvy = __ldg(kfr + 64 + 3 * tx + 1);
                float kvz = __ldg(kfr + 64 + 3 * tx + 2);
                float dx = dirs[r * 3 + 0], dy = dirs[r * 3 + 1], dz = dirs[r * 3 + 2];
                float dot = kvx * dx + kvy * dy + kvz * dz;
                float fs1 = w0 * ks1 + w4 * dot;
                float fs2 = w1 * ks2;
                float t1 = w3 * ks1;
                float fvx = w2 * kvx + t1 * dx + w5 * (kvy * dz - kvz * dy);
                float fvy = w2 * kvy + t1 * dy + w5 * (kvz * dx - kvx * dz);
                float fvz = w2 * kvz + t1 * dz + w5 * (kvx * dy - kvy * dx);
                int dst = dsts[r];
                if (dst != cur) {
                    if (cur >= 0) {
                        float* p = g_kfeat + (size_t)cur * FF;
                        atomicAdd(p + tx, a0 * curinv);
                        atomicAdd(p + 32 + tx, a1 * curinv);
                        atomicAdd(p + 64 + 3 * tx + 0, a2 * curinv);
                        atomicAdd(p + 64 + 3 * tx + 1, a3 * curinv);
                        atomicAdd(p + 64 + 3 * tx + 2, a4 * curinv);
                    }
                    cur = dst; curinv = invs[r];
                    a0 = fs1; a1 = fs2; a2 = fvx; a3 = fvy; a4 = fvz;
                } else {
                    a0 += fs1; a1 += fs2; a2 += fvx; a3 += fvy; a4 += fvz;
                }
            }
            if (cur >= 0) {
                float* p = g_kfeat + (size_t)cur * FF;
                atomicAdd(p + tx, a0 * curinv);
                atomicAdd(p + 32 + tx, a1 * curinv);
                atomicAdd(p + 64 + 3 * tx + 0, a2 * curinv);
                atomicAdd(p + 64 + 3 * tx + 1, a3 * curinv);
                atomicAdd(p + 64 + 3 * tx + 2, a4 * curinv);
            }
        }
    }
}

// ---------------- tensor-product heads + final reduction ----------------
__global__ __launch_bounds__(256) void tp_kernel(
    const float* __restrict__ query_f, const float* __restrict__ query_x,
    const float* __restrict__ query_w,
    const float* __restrict__ p00, const float* __restrict__ prest,
    const float* __restrict__ Ws_tp, const float* __restrict__ Wv_tp,
    float* __restrict__ out) {
    __shared__ float Wss[96 * 33];
    __shared__ float Wvs[96 * 32];
    __shared__ float s_sh[8][96];
    __shared__ float v_sh[8][96 * 3];
    __shared__ float accOut[6];
    int tid = threadIdx.x;
    int w = tid >> 5, c = tid & 31;
    int n = blockIdx.x * 8 + w;
    int t = n >> 8, q = n & 255;
    if (tid < 6) accOut[tid] = 0.0f;

    const float* kfr = g_kfeat + (size_t)n * FF;
    const float* qfr = query_f + (size_t)q * FF;
    float ks1 = kfr[c], ks2 = kfr[32 + c];
    float kvx = kfr[64 + 3 * c + 0], kvy = kfr[64 + 3 * c + 1], kvz = kfr[64 + 3 * c + 2];
    float qs1 = qfr[c], qs2 = qfr[32 + c];
    float qrx = qfr[64 + 3 * c + 0], qry = qfr[64 + 3 * c + 1], qrz = qfr[64 + 3 * c + 2];
    float R[9];
    #pragma unroll
    for (int i = 0; i < 9; i++) R[i] = __ldg(g_R + t * 9 + i);
    float qvx = R[0] * qrx + R[1] * qry + R[2] * qrz;
    float qvy = R[3] * qrx + R[4] * qry + R[5] * qrz;
    float qvz = R[6] * qrx + R[7] * qry + R[8] * qrz;

    float lin[3], ang[3];
    for (int head = 0; head < 2; head++) {
        __syncthreads();
        for (int i = tid; i < 96 * 33; i += 256) Wss[i] = Ws_tp[head * (96 * 33) + i];
        for (int i = tid; i < 96 * 32; i += 256) Wvs[i] = Wv_tp[head * (96 * 32) + i];
        __syncthreads();
        float p1 = __ldg(p00 + head * 64 + c);
        float p2 = __ldg(p00 + head * 64 + 32 + c);
        float pr0 = __ldg(prest + head * 128 + c);
        float pr1 = __ldg(prest + head * 128 + 32 + c);
        float pr2 = __ldg(prest + head * 128 + 64 + c);
        float pr3 = __ldg(prest + head * 128 + 96 + c);
        s_sh[w][c] = p1 * ks1 * qs1;
        s_sh[w][32 + c] = p2 * ks2 * qs2;
        s_sh[w][64 + c] = pr2 * (kvx * qvx + kvy * qvy + kvz * qvz);
        v_sh[w][3 * c + 0] = pr0 * kvx * qs1;
        v_sh[w][3 * c + 1] = pr0 * kvy * qs1;
        v_sh[w][3 * c + 2] = pr0 * kvz * qs1;
        v_sh[w][3 * (32 + c) + 0] = pr1 * ks1 * qvx;
        v_sh[w][3 * (32 + c) + 1] = pr1 * ks1 * qvy;
        v_sh[w][3 * (32 + c) + 2] = pr1 * ks1 * qvz;
        v_sh[w][3 * (64 + c) + 0] = pr3 * (kvy * qvz - kvz * qvy);
        v_sh[w][3 * (64 + c) + 1] = pr3 * (kvz * qvx - kvx * qvz);
        v_sh[w][3 * (64 + c) + 2] = pr3 * (kvx * qvy - kvy * qvx);
        __syncwarp();
        float sg = 0.0f, vmx = 0.0f, vmy = 0.0f, vmz = 0.0f;
        #pragma unroll 4
        for (int ch = 0; ch < 96; ch++) {
            float sv = s_sh[w][ch];
            sg += sv * Wss[ch * 33 + 1 + c];
            float wv = Wvs[ch * 32 + c];
            vmx += v_sh[w][3 * ch + 0] * wv;
            vmy += v_sh[w][3 * ch + 1] * wv;
            vmz += v_sh[w][3 * ch + 2] * wv;
        }
        float sig = 1.0f / (1.0f + __expf(-sg));
        float px = vmx * sig, py = vmy * sig, pz = vmz * sig;
        #pragma unroll
        for (int off = 16; off > 0; off >>= 1) {
            px += __shfl_xor_sync(0xffffffffu, px, off);
            py += __shfl_xor_sync(0xffffffffu, py, off);
            pz += __shfl_xor_sync(0xffffffffu, pz, off);
        }
        float sc = 1.0f / 32.0f;
        if (head == 0) { lin[0] = px * sc; lin[1] = py * sc; lin[2] = pz * sc; }
        else { ang[0] = px * sc; ang[1] = py * sc; ang[2] = pz * sc; }
        __syncwarp();
    }
    __syncthreads();
    if (c == 0) {
        float lwx = R[0] * lin[0] + R[3] * lin[1] + R[6] * lin[2];
        float lwy = R[1] * lin[0] + R[4] * lin[1] + R[7] * lin[2];
        float lwz = R[2] * lin[0] + R[5] * lin[1] + R[8] * lin[2];
        float awx = R[0] * ang[0] + R[3] * ang[1] + R[6] * ang[2];
        float awy = R[1] * ang[0] + R[4] * ang[1] + R[7] * ang[2];
        float awz = R[2] * ang[0] + R[5] * ang[1] + R[8] * ang[2];
        float qx0 = query_x[q * 3 + 0], qx1 = query_x[q * 3 + 1], qx2 = query_x[q * 3 + 2];
        float ox = qx1 * lwz - qx2 * lwy;
        float oy = qx2 * lwx - qx0 * lwz;
        float oz = qx0 * lwy - qx1 * lwx;
        float ww = query_w[q];
        atomicAdd(&accOut[0], ww * (ox + awx));
        atomicAdd(&accOut[1], ww * (oy + awy));
        atomicAdd(&accOut[2], ww * (oz + awz));
        atomicAdd(&accOut[3], ww * lwx);
        atomicAdd(&accOut[4], ww * lwy);
        atomicAdd(&accOut[5], ww * lwz);
    }
    __syncthreads();
    if (tid < 6) {
        int tt = blockIdx.x >> 5;
        int idx = (tid < 3) ? (tt * 3 + tid) : (NT * 3 + tt * 3 + (tid - 3));
        atomicAdd(out + idx, accOut[tid]);
    }
}

extern "C" void kernel_launch(void* const* d_in, const int* in_sizes, int n_in,
                              void* d_out, int out_size) {
    const float* Ts      = (const float*)d_in[0];
    const float* time_   = (const float*)d_in[1];
    const float* query_x = (const float*)d_in[2];
    const float* query_f = (const float*)d_in[3];
    const float* query_w = (const float*)d_in[4];
    const float* kx0     = (const float*)d_in[5];
    const float* kf0     = (const float*)d_in[6];
    const float* kx1     = (const float*)d_in[7];
    const float* kf1     = (const float*)d_in[8];
    const int*   es0     = (const int*)d_in[9];
    const int*   ed0     = (const int*)d_in[10];
    const int*   es1     = (const int*)d_in[11];
    const int*   ed1     = (const int*)d_in[12];
    const float* W_qt    = (const float*)d_in[13];
    const float* b_qt    = (const float*)d_in[14];
    const float* W1_r    = (const float*)d_in[15];
    const float* b1_r    = (const float*)d_in[16];
    const float* W2_r    = (const float*)d_in[17];
    const float* b2_r    = (const float*)d_in[18];
    const float* p00     = (const float*)d_in[19];
    const float* prest   = (const float*)d_in[20];
    const float* Ws_tp   = (const float*)d_in[21];
    const float* Wv_tp   = (const float*)d_in[22];
    float* out = (float*)d_out;

    cudaFuncSetAttribute(edge_mma_kernel, cudaFuncAttributeMaxDynamicSharedMemorySize,
                         EDGE_SMEM);

    zero_kernel<<<2048, 256>>>(out);
    hist_kernel<<<1024, 256>>>(ed0, ed1);
    scan_kernel<<<1, 1024>>>();
    prep_kernel<<<NT, 128>>>(Ts, time_, query_x, W_qt, b_qt, W1_r, b1_r);
    scatter_kernel<<<512, 256>>>(es0, ed0, es1, ed1);
    edge_mma_kernel<<<148, 256, EDGE_SMEM>>>(kx0, kf0, kx1, kf1, W1_r, W2_r, b2_r);
    tp_kernel<<<NN / 8, 256>>>(query_f, query_x, query_w, p00, prest, Ws_tp, Wv_tp, out);
}

// round 7
// speedup vs baseline: 1.3040x; 1.3040x over previous
#include <cuda_runtime.h>
#include <cuda_bf16.h>
#include <math.h>
#include <stdint.h>

#define NT 64
#define NQ 256
#define NPK 100000
#define NE 262144
#define NN 16384
#define DS 64
#define DV 32
#define TEH 128
#define FF 160

#define TILE_E 128
#define TILES2 2048          // tiles per scale (NE / 128)
#define BPS 74               // blocks per scale (148 total)
#define HSTR 196             // Hs row stride (floats)
#define ASTR 37              // A row stride (32-bit words; 74 bf16)
#define NTHREADS 512

// smem byte offsets
#define OFF_BF   0           // B fragments: 192 frags x 32 lanes x 8 B = 49152
#define OFF_AHI  49152       // 128 x 37 words = 18944
#define OFF_ALO  68096       // 18944
#define OFF_HS   87040       // 128 x 196 floats = 100352
#define OFF_RBS  187392      // 128 x 9 floats = 4608
#define OFF_DIRS 192000      // 1536
#define OFF_INVS 193536      // 512
#define OFF_SRCS 194048      // 512
#define OFF_DSTS 194560      // 512
#define OFF_TTS  195072      // 512
#define OFF_W1S  195584      // 2048
#define OFF_B2S  197632      // 768
#define EDGE_SMEM 198400

__device__ float g_kfeat[NN * FF];
__device__ int   g_cnt[2 * NN];
__device__ int   g_cur[2 * NN];
__device__ float g_invcnt[2 * NN];
__device__ float g_qx[NN * 3];
__device__ float g_R[NT * 9];
__device__ float g_pre[2 * NT * 64];
__device__ int2  g_srt[2 * NE];

__device__ __forceinline__ unsigned short bfbits(float v) {
    __nv_bfloat16 b = __float2bfloat16_rn(v);
    return *reinterpret_cast<unsigned short*>(&b);
}
__device__ __forceinline__ float bf2f(unsigned short u) {
    __nv_bfloat16 b = *reinterpret_cast<__nv_bfloat16*>(&u);
    return __bfloat162float(b);
}

#define MMA_BF16(c, a, b) \
    asm volatile("mma.sync.aligned.m16n8k16.row.col.f32.bf16.bf16.f32 " \
        "{%0,%1,%2,%3}, {%4,%5,%6,%7}, {%8,%9}, {%0,%1,%2,%3};" \
        : "+f"((c)[0]), "+f"((c)[1]), "+f"((c)[2]), "+f"((c)[3]) \
        : "r"((a)[0]), "r"((a)[1]), "r"((a)[2]), "r"((a)[3]), \
          "r"((b)[0]), "r"((b)[1]))

// ---------------- small kernels ----------------
__global__ void zero_kernel(float* __restrict__ out) {
    int i = blockIdx.x * blockDim.x + threadIdx.x;
    int st = gridDim.x * blockDim.x;
    for (int z = i; z < NN * FF; z += st) g_kfeat[z] = 0.0f;
    for (int z = i; z < 2 * NN; z += st) g_cnt[z] = 0;
    if (i < 2 * NT * 3) out[i] = 0.0f;
}

__global__ void hist_kernel(const int* __restrict__ ed0, const int* __restrict__ ed1) {
    int i = blockIdx.x * blockDim.x + threadIdx.x;
    int st = gridDim.x * blockDim.x;
    for (int e = i; e < NE; e += st) atomicAdd(&g_cnt[ed0[e]], 1);
    for (int e = i; e < NE; e += st) atomicAdd(&g_cnt[NN + ed1[e]], 1);
}

__global__ void scan_kernel() {
    __shared__ int sm[1024];
    int tid = threadIdx.x;
    int base = tid * 32;
    int loc[32];
    int s = 0;
    #pragma unroll
    for (int i = 0; i < 32; i++) { loc[i] = g_cnt[base + i]; s += loc[i]; }
    sm[tid] = s;
    __syncthreads();
    for (int off = 1; off < 1024; off <<= 1) {
        int v = (tid >= off) ? sm[tid - off] : 0;
        __syncthreads();
        sm[tid] += v;
        __syncthreads();
    }
    int ex = sm[tid] - s;
    #pragma unroll
    for (int i = 0; i < 32; i++) { g_cur[base + i] = ex; ex += loc[i]; }
}

__global__ void scatter_kernel(const int* __restrict__ es0, const int* __restrict__ ed0,
                               const int* __restrict__ es1, const int* __restrict__ ed1) {
    int i = blockIdx.x * blockDim.x + threadIdx.x;
    int st = gridDim.x * blockDim.x;
    for (int e = i; e < NE; e += st) {
        int d = ed0[e];
        int pos = atomicAdd(&g_cur[d], 1);
        g_srt[pos] = make_int2(es0[e], d);
    }
    for (int e = i; e < NE; e += st) {
        int d = ed1[e];
        int pos = atomicAdd(&g_cur[NN + d], 1);
        g_srt[pos] = make_int2(es1[e], d);
    }
}

__global__ void prep_kernel(const float* __restrict__ Ts, const float* __restrict__ time_,
                            const float* __restrict__ query_x,
                            const float* __restrict__ W_qt, const float* __restrict__ b_qt,
                            const float* __restrict__ W1_r, const float* __restrict__ b1_r) {
    __shared__ float te[128];
    __shared__ float qemb[128];
    __shared__ float Rsh[9];
    __shared__ float tsh[3];
    int t = blockIdx.x;
    int tid = threadIdx.x;  // 128 threads
    float tv = time_[t];
    {
        int k = tid & 63;
        float f = __expf(-logf(10000.0f) * (float)k / 63.0f);
        float a = tv * f;
        te[tid] = (tid < 64) ? sinf(a) : cosf(a);
    }
    if (tid == 0) {
        float qw = Ts[t * 7 + 0], qa = Ts[t * 7 + 1], qb = Ts[t * 7 + 2], qc = Ts[t * 7 + 3];
        float nrm = rsqrtf(qw * qw + qa * qa + qb * qb + qc * qc);
        qw *= nrm; qa *= nrm; qb *= nrm; qc *= nrm;
        Rsh[0] = 1.0f - 2.0f * (qb * qb + qc * qc);
        Rsh[1] = 2.0f * (qa * qb - qw * qc);
        Rsh[2] = 2.0f * (qa * qc + qw * qb);
        Rsh[3] = 2.0f * (qa * qb + qw * qc);
        Rsh[4] = 1.0f - 2.0f * (qa * qa + qc * qc);
        Rsh[5] = 2.0f * (qb * qc - qw * qa);
        Rsh[6] = 2.0f * (qa * qc - qw * qb);
        Rsh[7] = 2.0f * (qb * qc + qw * qa);
        Rsh[8] = 1.0f - 2.0f * (qa * qa + qb * qb);
        tsh[0] = Ts[t * 7 + 4]; tsh[1] = Ts[t * 7 + 5]; tsh[2] = Ts[t * 7 + 6];
        #pragma unroll
        for (int i = 0; i < 9; i++) g_R[t * 9 + i] = Rsh[i];
    }
    __syncthreads();
    {
        int o = tid;
        float acc = b_qt[o];
        for (int k = 0; k < 128; k++) acc += te[k] * W_qt[k * TEH + o];
        qemb[o] = acc;
    }
    __syncthreads();
    {
        int s = tid >> 6, j = tid & 63;
        float acc = b1_r[s * 64 + j];
        const float* w = W1_r + s * 136 * 64 + 8 * 64 + j;
        for (int i = 0; i < 128; i++) acc += qemb[i] * w[i * 64];
        g_pre[(s * NT + t) * 64 + j] = acc;
    }
    for (int q = tid; q < NQ; q += blockDim.x) {
        float x = query_x[q * 3 + 0], y = query_x[q * 3 + 1], z = query_x[q * 3 + 2];
        int n = t * NQ + q;
        g_qx[n * 3 + 0] = Rsh[0] * x + Rsh[1] * y + Rsh[2] * z + tsh[0];
        g_qx[n * 3 + 1] = Rsh[3] * x + Rsh[4] * y + Rsh[5] * z + tsh[1];
        g_qx[n * 3 + 2] = Rsh[6] * x + Rsh[7] * y + Rsh[8] * z + tsh[2];
    }
    int gtid = t * blockDim.x + tid;
    int gst = gridDim.x * blockDim.x;
    for (int z = gtid; z < 2 * NN; z += gst)
        g_invcnt[z] = 1.0f / ((float)g_cnt[z] + 1e-8f);
}

// ---------------- fused edge kernel: mma.sync bf16x3, 16 warps ----------------
// 148 persistent blocks of 512 threads; even blocks scale 0, odd scale 1;
// 128-edge tiles. H[128x192] = silu(layer1)[128x64] @ W2[64x192] via bf16 mma
// with 2-split/3-product fp32-grade accuracy. Warp (cg, rh): 24 cols x 64 rows.
// B fragments read from smem (keeps regs low for 512-thread occupancy).
__global__ __launch_bounds__(NTHREADS, 1)
void edge_mma_kernel(
    const float* __restrict__ kx0, const float* __restrict__ kf0,
    const float* __restrict__ kx1, const float* __restrict__ kf1,
    const float* __restrict__ W1_r, const float* __restrict__ W2_r,
    const float* __restrict__ b2_r) {
    extern __shared__ char smem[];
    int tid = threadIdx.x;
    int wid = tid >> 5, lane = tid & 31;
    int quad = lane >> 2, lm4 = lane & 3;
    int s = blockIdx.x & 1;
    int tstart = blockIdx.x >> 1;

    const float* kx = s ? kx1 : kx0;
    const float* kf = s ? kf1 : kf0;
    const float* preS = g_pre + s * NT * 64;
    const float* icS = g_invcnt + s * NN;
    const int2* srtS = g_srt + s * NE;

    uint2*  Bf2  = (uint2*)(smem + OFF_BF);
    uint32_t* Ahw = (uint32_t*)(smem + OFF_AHI);
    uint32_t* Alw = (uint32_t*)(smem + OFF_ALO);
    float* Hs   = (float*)(smem + OFF_HS);
    float* rbs  = (float*)(smem + OFF_RBS);
    float* dirs = (float*)(smem + OFF_DIRS);
    float* invs = (float*)(smem + OFF_INVS);
    int*   srcs = (int*)(smem + OFF_SRCS);
    int*   dsts = (int*)(smem + OFF_DSTS);
    int*   tts  = (int*)(smem + OFF_TTS);
    float* W1s  = (float*)(smem + OFF_W1S);
    float* b2s  = (float*)(smem + OFF_B2S);

    // --- prologue: W1, b2, B-fragment pack (hi/lo bf16) ---
    for (int i = tid; i < 512; i += NTHREADS) W1s[i] = W1_r[s * (136 * 64) + i];
    for (int i = tid; i < 192; i += NTHREADS) b2s[i] = b2_r[s * 192 + i];
    // fragment id f = (sp*4 + kt)*24 + gn ; entry (f, lane)
    for (int idx = tid; idx < 6144; idx += NTHREADS) {
        int l = idx & 31;
        int f = idx >> 5;
        int gn = f % 24;
        int kt = (f / 24) & 3;
        int sp = f / 96;
        int n = gn * 8 + (l >> 2);
        int k0 = kt * 16 + (l & 3) * 2;
        const float* w2 = W2_r + s * 12288;
        float v00 = w2[k0 * 192 + n];
        float v01 = w2[(k0 + 1) * 192 + n];
        float v10 = w2[(k0 + 8) * 192 + n];
        float v11 = w2[(k0 + 9) * 192 + n];
        uint32_t r0, r1;
        if (sp == 0) {
            r0 = (uint32_t)bfbits(v00) | ((uint32_t)bfbits(v01) << 16);
            r1 = (uint32_t)bfbits(v10) | ((uint32_t)bfbits(v11) << 16);
        } else {
            unsigned short h00 = bfbits(v00), h01 = bfbits(v01);
            unsigned short h10 = bfbits(v10), h11 = bfbits(v11);
            r0 = (uint32_t)bfbits(v00 - bf2f(h00)) | ((uint32_t)bfbits(v01 - bf2f(h01)) << 16);
            r1 = (uint32_t)bfbits(v10 - bf2f(h10)) | ((uint32_t)bfbits(v11 - bf2f(h11)) << 16);
        }
        Bf2[f * 32 + l] = make_uint2(r0, r1);
    }
    __syncthreads();

    int cg = wid & 7;       // column group: cols [24cg, 24cg+24)
    int rh = wid >> 3;      // row half: rows [64rh, 64rh+64)

    for (int tile = tstart; tile < TILES2; tile += BPS) {
        __syncthreads();
        // phase 1: per-edge geometry + rbf (dst-sorted edges)
        if (tid < TILE_E) {
            int2 sd = srtS[tile * TILE_E + tid];
            int src = sd.x, dst = sd.y;
            float rx = kx[src * 3 + 0] - g_qx[dst * 3 + 0];
            float ry = kx[src * 3 + 1] - g_qx[dst * 3 + 1];
            float rz = kx[src * 3 + 2] - g_qx[dst * 3 + 2];
            float r = sqrtf(rx * rx + ry * ry + rz * rz);
            float ir = 1.0f / (r + 1e-8f);
            dirs[tid * 3 + 0] = rx * ir;
            dirs[tid * 3 + 1] = ry * ir;
            dirs[tid * 3 + 2] = rz * ir;
            #pragma unroll
            for (int i = 0; i < 8; i++) {
                float dcl = r - (4.0f / 7.0f) * (float)i;
                rbs[tid * 9 + i] = __expf(-dcl * dcl * 4.0f);
            }
            invs[tid] = icS[dst];
            srcs[tid] = src; dsts[tid] = dst; tts[tid] = dst >> 8;
        }
        __syncthreads();

        // phase 2: layer1 + silu -> bf16 hi/lo into A smem (16 j per thread)
        {
            int row = tid & 127;
            int jr = (tid >> 7) * 16;
            float rb[8];
            #pragma unroll
            for (int i = 0; i < 8; i++) rb[i] = rbs[row * 9 + i];
            const float* prow = preS + tts[row] * 64;
            uint32_t hw[8], lw[8];
            #pragma unroll
            for (int p = 0; p < 8; p++) {
                float av[2];
                #pragma unroll
                for (int q = 0; q < 2; q++) {
                    int j = jr + p * 2 + q;
                    float h = __ldg(prow + j);
                    #pragma unroll
                    for (int i = 0; i < 8; i++) h += rb[i] * W1s[i * 64 + j];
                    av[q] = h * (1.0f / (1.0f + __expf(-h)));
                }
                unsigned short h0 = bfbits(av[0]), h1 = bfbits(av[1]);
                hw[p] = (uint32_t)h0 | ((uint32_t)h1 << 16);
                lw[p] = (uint32_t)bfbits(av[0] - bf2f(h0)) |
                        ((uint32_t)bfbits(av[1] - bf2f(h1)) << 16);
            }
            uint32_t base = row * ASTR + (jr >> 1);
            #pragma unroll
            for (int p = 0; p < 8; p++) { Ahw[base + p] = hw[p]; Alw[base + p] = lw[p]; }
        }
        __syncthreads();

        // phase 3: GEMM. warp (cg, rh): cols [24cg,24cg+24), rows [64rh,64rh+64).
        float acc[3][4][4];
        #pragma unroll
        for (int nt = 0; nt < 3; nt++)
            #pragma unroll
            for (int mc = 0; mc < 4; mc++)
                #pragma unroll
                for (int r = 0; r < 4; r++) acc[nt][mc][r] = 0.0f;

        #pragma unroll
        for (int mc = 0; mc < 4; mc++) {
            int r0 = rh * 64 + mc * 16 + quad;
            uint32_t ah[4][4], al[4][4];
            #pragma unroll
            for (int kt = 0; kt < 4; kt++) {
                uint32_t b0 = r0 * ASTR + kt * 8 + lm4;
                uint32_t b1 = (r0 + 8) * ASTR + kt * 8 + lm4;
                ah[kt][0] = Ahw[b0];     ah[kt][1] = Ahw[b1];
                ah[kt][2] = Ahw[b0 + 4]; ah[kt][3] = Ahw[b1 + 4];
                al[kt][0] = Alw[b0];     al[kt][1] = Alw[b1];
                al[kt][2] = Alw[b0 + 4]; al[kt][3] = Alw[b1 + 4];
            }
            #pragma unroll
            for (int nt = 0; nt < 3; nt++)
                #pragma unroll
                for (int kt = 0; kt < 4; kt++) {
                    int gf = cg * 3 + nt;
                    uint2 bh = Bf2[(kt * 24 + gf) * 32 + lane];
                    uint2 bl = Bf2[((4 + kt) * 24 + gf) * 32 + lane];
                    uint32_t bhv[2] = {bh.x, bh.y};
                    uint32_t blv[2] = {bl.x, bl.y};
                    MMA_BF16(acc[nt][mc], ah[kt], bhv);
                    MMA_BF16(acc[nt][mc], al[kt], bhv);
                    MMA_BF16(acc[nt][mc], ah[kt], blv);
                }
        }

        // phase 4: accumulators (+bias) -> Hs slab
        #pragma unroll
        for (int nt = 0; nt < 3; nt++) {
            int col = cg * 24 + nt * 8 + lm4 * 2;
            float bb0 = b2s[col], bb1 = b2s[col + 1];
            #pragma unroll
            for (int mc = 0; mc < 4; mc++) {
                int row = rh * 64 + mc * 16 + quad;
                float2 v0 = make_float2(acc[nt][mc][0] + bb0, acc[nt][mc][1] + bb1);
                float2 v1 = make_float2(acc[nt][mc][2] + bb0, acc[nt][mc][3] + bb1);
                *(float2*)&Hs[row * HSTR + col] = v0;
                *(float2*)&Hs[(row + 8) * HSTR + col] = v1;
            }
        }
        __syncthreads();

        // phase 5: message + run-merged atomic scatter. warp wid: edges [8w, 8w+8)
        {
            int tx = lane;
            float a0 = 0.f, a1 = 0.f, a2 = 0.f, a3 = 0.f, a4 = 0.f;
            float curinv = 0.f;
            int cur = -1;
            #pragma unroll
            for (int e8 = 0; e8 < 8; e8++) {
                int r = wid * 8 + e8;
                float w0 = Hs[r * HSTR + tx];
                float w1 = Hs[r * HSTR + 32 + tx];
                float w2 = Hs[r * HSTR + 64 + tx];
                float w3 = Hs[r * HSTR + 96 + tx];
                float w4 = Hs[r * HSTR + 128 + tx];
                float w5 = Hs[r * HSTR + 160 + tx];
                const float* kfr = kf + (size_t)srcs[r] * FF;
                float ks1 = __ldg(kfr + tx);
                float ks2 = __ldg(kfr + 32 + tx);
                float kvx = __ldg(kfr + 64 + 3 * tx + 0);
                float kvy = __ldg(kfr + 64 + 3 * tx + 1);
                float kvz = __ldg(kfr + 64 + 3 * tx + 2);
                float dx = dirs[r * 3 + 0], dy = dirs[r * 3 + 1], dz = dirs[r * 3 + 2];
                float dot = kvx * dx + kvy * dy + kvz * dz;
                float fs1 = w0 * ks1 + w4 * dot;
                float fs2 = w1 * ks2;
                float t1 = w3 * ks1;
                float fvx = w2 * kvx + t1 * dx + w5 * (kvy * dz - kvz * dy);
                float fvy = w2 * kvy + t1 * dy + w5 * (kvz * dx - kvx * dz);
                float fvz = w2 * kvz + t1 * dz + w5 * (kvx * dy - kvy * dx);
                int dst = dsts[r];
                if (dst != cur) {
                    if (cur >= 0) {
                        float* p = g_kfeat + (size_t)cur * FF;
                        atomicAdd(p + tx, a0 * curinv);
                        atomicAdd(p + 32 + tx, a1 * curinv);
                        atomicAdd(p + 64 + 3 * tx + 0, a2 * curinv);
                        atomicAdd(p + 64 + 3 * tx + 1, a3 * curinv);
                        atomicAdd(p + 64 + 3 * tx + 2, a4 * curinv);
                    }
                    cur = dst; curinv = invs[r];
                    a0 = fs1; a1 = fs2; a2 = fvx; a3 = fvy; a4 = fvz;
                } else {
                    a0 += fs1; a1 += fs2; a2 += fvx; a3 += fvy; a4 += fvz;
                }
            }
            if (cur >= 0) {
                float* p = g_kfeat + (size_t)cur * FF;
                atomicAdd(p + tx, a0 * curinv);
                atomicAdd(p + 32 + tx, a1 * curinv);
                atomicAdd(p + 64 + 3 * tx + 0, a2 * curinv);
                atomicAdd(p + 64 + 3 * tx + 1, a3 * curinv);
                atomicAdd(p + 64 + 3 * tx + 2, a4 * curinv);
            }
        }
    }
}

// ---------------- tensor-product heads + final reduction ----------------
__global__ __launch_bounds__(256) void tp_kernel(
    const float* __restrict__ query_f, const float* __restrict__ query_x,
    const float* __restrict__ query_w,
    const float* __restrict__ p00, const float* __restrict__ prest,
    const float* __restrict__ Ws_tp, const float* __restrict__ Wv_tp,
    float* __restrict__ out) {
    __shared__ float Wss[96 * 33];
    __shared__ float Wvs[96 * 32];
    __shared__ float s_sh[8][96];
    __shared__ float v_sh[8][96 * 3];
    __shared__ float accOut[6];
    int tid = threadIdx.x;
    int w = tid >> 5, c = tid & 31;
    int n = blockIdx.x * 8 + w;
    int t = n >> 8, q = n & 255;
    if (tid < 6) accOut[tid] = 0.0f;

    const float* kfr = g_kfeat + (size_t)n * FF;
    const float* qfr = query_f + (size_t)q * FF;
    float ks1 = kfr[c], ks2 = kfr[32 + c];
    float kvx = kfr[64 + 3 * c + 0], kvy = kfr[64 + 3 * c + 1], kvz = kfr[64 + 3 * c + 2];
    float qs1 = qfr[c], qs2 = qfr[32 + c];
    float qrx = qfr[64 + 3 * c + 0], qry = qfr[64 + 3 * c + 1], qrz = qfr[64 + 3 * c + 2];
    float R[9];
    #pragma unroll
    for (int i = 0; i < 9; i++) R[i] = __ldg(g_R + t * 9 + i);
    float qvx = R[0] * qrx + R[1] * qry + R[2] * qrz;
    float qvy = R[3] * qrx + R[4] * qry + R[5] * qrz;
    float qvz = R[6] * qrx + R[7] * qry + R[8] * qrz;

    float lin[3], ang[3];
    for (int head = 0; head < 2; head++) {
        __syncthreads();
        for (int i = tid; i < 96 * 33; i += 256) Wss[i] = Ws_tp[head * (96 * 33) + i];
        for (int i = tid; i < 96 * 32; i += 256) Wvs[i] = Wv_tp[head * (96 * 32) + i];
        __syncthreads();
        float p1 = __ldg(p00 + head * 64 + c);
        float p2 = __ldg(p00 + head * 64 + 32 + c);
        float pr0 = __ldg(prest + head * 128 + c);
        float pr1 = __ldg(prest + head * 128 + 32 + c);
        float pr2 = __ldg(prest + head * 128 + 64 + c);
        float pr3 = __ldg(prest + head * 128 + 96 + c);
        s_sh[w][c] = p1 * ks1 * qs1;
        s_sh[w][32 + c] = p2 * ks2 * qs2;
        s_sh[w][64 + c] = pr2 * (kvx * qvx + kvy * qvy + kvz * qvz);
        v_sh[w][3 * c + 0] = pr0 * kvx * qs1;
        v_sh[w][3 * c + 1] = pr0 * kvy * qs1;
        v_sh[w][3 * c + 2] = pr0 * kvz * qs1;
        v_sh[w][3 * (32 + c) + 0] = pr1 * ks1 * qvx;
        v_sh[w][3 * (32 + c) + 1] = pr1 * ks1 * qvy;
        v_sh[w][3 * (32 + c) + 2] = pr1 * ks1 * qvz;
        v_sh[w][3 * (64 + c) + 0] = pr3 * (kvy * qvz - kvz * qvy);
        v_sh[w][3 * (64 + c) + 1] = pr3 * (kvz * qvx - kvx * qvz);
        v_sh[w][3 * (64 + c) + 2] = pr3 * (kvx * qvy - kvy * qvx);
        __syncwarp();
        float sg = 0.0f, vmx = 0.0f, vmy = 0.0f, vmz = 0.0f;
        #pragma unroll 4
        for (int ch = 0; ch < 96; ch++) {
            float sv = s_sh[w][ch];
            sg += sv * Wss[ch * 33 + 1 + c];
            float wv = Wvs[ch * 32 + c];
            vmx += v_sh[w][3 * ch + 0] * wv;
            vmy += v_sh[w][3 * ch + 1] * wv;
            vmz += v_sh[w][3 * ch + 2] * wv;
        }
        float sig = 1.0f / (1.0f + __expf(-sg));
        float px = vmx * sig, py = vmy * sig, pz = vmz * sig;
        #pragma unroll
        for (int off = 16; off > 0; off >>= 1) {
            px += __shfl_xor_sync(0xffffffffu, px, off);
            py += __shfl_xor_sync(0xffffffffu, py, off);
            pz += __shfl_xor_sync(0xffffffffu, pz, off);
        }
        float sc = 1.0f / 32.0f;
        if (head == 0) { lin[0] = px * sc; lin[1] = py * sc; lin[2] = pz * sc; }
        else { ang[0] = px * sc; ang[1] = py * sc; ang[2] = pz * sc; }
        __syncwarp();
    }
    __syncthreads();
    if (c == 0) {
        float lwx = R[0] * lin[0] + R[3] * lin[1] + R[6] * lin[2];
        float lwy = R[1] * lin[0] + R[4] * lin[1] + R[7] * lin[2];
        float lwz = R[2] * lin[0] + R[5] * lin[1] + R[8] * lin[2];
        float awx = R[0] * ang[0] + R[3] * ang[1] + R[6] * ang[2];
        float awy = R[1] * ang[0] + R[4] * ang[1] + R[7] * ang[2];
        float awz = R[2] * ang[0] + R[5] * ang[1] + R[8] * ang[2];
        float qx0 = query_x[q * 3 + 0], qx1 = query_x[q * 3 + 1], qx2 = query_x[q * 3 + 2];
        float ox = qx1 * lwz - qx2 * lwy;
        float oy = qx2 * lwx - qx0 * lwz;
        float oz = qx0 * lwy - qx1 * lwx;
        float ww = query_w[q];
        atomicAdd(&accOut[0], ww * (ox + awx));
        atomicAdd(&accOut[1], ww * (oy + awy));
        atomicAdd(&accOut[2], ww * (oz + awz));
        atomicAdd(&accOut[3], ww * lwx);
        atomicAdd(&accOut[4], ww * lwy);
        atomicAdd(&accOut[5], ww * lwz);
    }
    __syncthreads();
    if (tid < 6) {
        int tt = blockIdx.x >> 5;
        int idx = (tid < 3) ? (tt * 3 + tid) : (NT * 3 + tt * 3 + (tid - 3));
        atomicAdd(out + idx, accOut[tid]);
    }
}

extern "C" void kernel_launch(void* const* d_in, const int* in_sizes, int n_in,
                              void* d_out, int out_size) {
    const float* Ts      = (const float*)d_in[0];
    const float* time_   = (const float*)d_in[1];
    const float* query_x = (const float*)d_in[2];
    const float* query_f = (const float*)d_in[3];
    const float* query_w = (const float*)d_in[4];
    const float* kx0     = (const float*)d_in[5];
    const float* kf0     = (const float*)d_in[6];
    const float* kx1     = (const float*)d_in[7];
    const float* kf1     = (const float*)d_in[8];
    const int*   es0     = (const int*)d_in[9];
    const int*   ed0     = (const int*)d_in[10];
    const int*   es1     = (const int*)d_in[11];
    const int*   ed1     = (const int*)d_in[12];
    const float* W_qt    = (const float*)d_in[13];
    const float* b_qt    = (const float*)d_in[14];
    const float* W1_r    = (const float*)d_in[15];
    const float* b1_r    = (const float*)d_in[16];
    const float* W2_r    = (const float*)d_in[17];
    const float* b2_r    = (const float*)d_in[18];
    const float* p00     = (const float*)d_in[19];
    const float* prest   = (const float*)d_in[20];
    const float* Ws_tp   = (const float*)d_in[21];
    const float* Wv_tp   = (const float*)d_in[22];
    float* out = (float*)d_out;

    cudaFuncSetAttribute(edge_mma_kernel, cudaFuncAttributeMaxDynamicSharedMemorySize,
                         EDGE_SMEM);

    zero_kernel<<<2048, 256>>>(out);
    hist_kernel<<<1024, 256>>>(ed0, ed1);
    scan_kernel<<<1, 1024>>>();
    prep_kernel<<<NT, 128>>>(Ts, time_, query_x, W_qt, b_qt, W1_r, b1_r);
    scatter_kernel<<<512, 256>>>(es0, ed0, es1, ed1);
    edge_mma_kernel<<<148, NTHREADS, EDGE_SMEM>>>(kx0, kf0, kx1, kf1, W1_r, W2_r, b2_r);
    tp_kernel<<<NN / 8, 256>>>(query_f, query_x, query_w, p00, prest, Ws_tp, Wv_tp, out);
}

// round 8
// speedup vs baseline: 1.6560x; 1.2700x over previous
#include <cuda_runtime.h>
#include <cuda_bf16.h>
#include <cuda_fp16.h>
#include <math.h>
#include <stdint.h>

#define NT 64
#define NQ 256
#define NPK 100000
#define NE 262144
#define NN 16384
#define DS 64
#define DV 32
#define TEH 128
#define FF 160

#define TILE_E 128
#define TILES2 2048          // tiles per scale (NE / 128)
#define BPS 74               // blocks per scale (148 total)
#define HSTR 196             // Hs row stride (floats)
#define ASTR 37              // A row stride (32-bit words; 64 fp16 = 32 words + pad)
#define NTHREADS 512

// smem byte offsets
#define OFF_BF   0           // B fragments: 96 frags x 32 lanes x 8 B = 24576
#define OFF_A    24576       // 128 x 37 words = 18944
#define OFF_HS   43520       // 128 x 196 floats = 100352
#define OFF_RBS  143872      // 128 x 9 floats = 4608
#define OFF_DIRS 148480      // 1536
#define OFF_INVS 150016      // 512
#define OFF_SRCS 150528      // 512
#define OFF_DSTS 151040      // 512
#define OFF_TTS  151552      // 512
#define OFF_W1S  152064      // 2048
#define OFF_B2S  154112      // 768
#define EDGE_SMEM 154880

__device__ float g_kfeat[NN * FF];
__device__ int   g_cnt[2 * NN];
__device__ int   g_cur[2 * NN];
__device__ float g_invcnt[2 * NN];
__device__ float g_qx[NN * 3];
__device__ float g_R[NT * 9];
__device__ float g_pre[2 * NT * 64];
__device__ int2  g_srt[2 * NE];

__device__ __forceinline__ uint32_t pack_half2(float a, float b) {
    __half2 h = __floats2half2_rn(a, b);
    return *reinterpret_cast<uint32_t*>(&h);
}

#define MMA_F16(c, a, b) \
    asm volatile("mma.sync.aligned.m16n8k16.row.col.f32.f16.f16.f32 " \
        "{%0,%1,%2,%3}, {%4,%5,%6,%7}, {%8,%9}, {%0,%1,%2,%3};" \
        : "+f"((c)[0]), "+f"((c)[1]), "+f"((c)[2]), "+f"((c)[3]) \
        : "r"((a)[0]), "r"((a)[1]), "r"((a)[2]), "r"((a)[3]), \
          "r"((b)[0]), "r"((b)[1]))

// ---------------- small kernels ----------------
__global__ void zero_kernel(float* __restrict__ out) {
    int i = blockIdx.x * blockDim.x + threadIdx.x;
    int st = gridDim.x * blockDim.x;
    for (int z = i; z < NN * FF; z += st) g_kfeat[z] = 0.0f;
    for (int z = i; z < 2 * NN; z += st) g_cnt[z] = 0;
    if (i < 2 * NT * 3) out[i] = 0.0f;
}

__global__ void hist_kernel(const int* __restrict__ ed0, const int* __restrict__ ed1) {
    int i = blockIdx.x * blockDim.x + threadIdx.x;
    int st = gridDim.x * blockDim.x;
    for (int e = i; e < NE; e += st) atomicAdd(&g_cnt[ed0[e]], 1);
    for (int e = i; e < NE; e += st) atomicAdd(&g_cnt[NN + ed1[e]], 1);
}

__global__ void scan_kernel() {
    __shared__ int sm[1024];
    int tid = threadIdx.x;
    int base = tid * 32;
    int loc[32];
    int s = 0;
    #pragma unroll
    for (int i = 0; i < 32; i++) { loc[i] = g_cnt[base + i]; s += loc[i]; }
    sm[tid] = s;
    __syncthreads();
    for (int off = 1; off < 1024; off <<= 1) {
        int v = (tid >= off) ? sm[tid - off] : 0;
        __syncthreads();
        sm[tid] += v;
        __syncthreads();
    }
    int ex = sm[tid] - s;
    #pragma unroll
    for (int i = 0; i < 32; i++) { g_cur[base + i] = ex; ex += loc[i]; }
}

__global__ void scatter_kernel(const int* __restrict__ es0, const int* __restrict__ ed0,
                               const int* __restrict__ es1, const int* __restrict__ ed1) {
    int i = blockIdx.x * blockDim.x + threadIdx.x;
    int st = gridDim.x * blockDim.x;
    for (int e = i; e < NE; e += st) {
        int d = ed0[e];
        int pos = atomicAdd(&g_cur[d], 1);
        g_srt[pos] = make_int2(es0[e], d);
    }
    for (int e = i; e < NE; e += st) {
        int d = ed1[e];
        int pos = atomicAdd(&g_cur[NN + d], 1);
        g_srt[pos] = make_int2(es1[e], d);
    }
}

__global__ void prep_kernel(const float* __restrict__ Ts, const float* __restrict__ time_,
                            const float* __restrict__ query_x,
                            const float* __restrict__ W_qt, const float* __restrict__ b_qt,
                            const float* __restrict__ W1_r, const float* __restrict__ b1_r) {
    __shared__ float te[128];
    __shared__ float qemb[128];
    __shared__ float Rsh[9];
    __shared__ float tsh[3];
    int t = blockIdx.x;
    int tid = threadIdx.x;  // 128 threads
    float tv = time_[t];
    {
        int k = tid & 63;
        float f = __expf(-logf(10000.0f) * (float)k / 63.0f);
        float a = tv * f;
        te[tid] = (tid < 64) ? sinf(a) : cosf(a);
    }
    if (tid == 0) {
        float qw = Ts[t * 7 + 0], qa = Ts[t * 7 + 1], qb = Ts[t * 7 + 2], qc = Ts[t * 7 + 3];
        float nrm = rsqrtf(qw * qw + qa * qa + qb * qb + qc * qc);
        qw *= nrm; qa *= nrm; qb *= nrm; qc *= nrm;
        Rsh[0] = 1.0f - 2.0f * (qb * qb + qc * qc);
        Rsh[1] = 2.0f * (qa * qb - qw * qc);
        Rsh[2] = 2.0f * (qa * qc + qw * qb);
        Rsh[3] = 2.0f * (qa * qb + qw * qc);
        Rsh[4] = 1.0f - 2.0f * (qa * qa + qc * qc);
        Rsh[5] = 2.0f * (qb * qc - qw * qa);
        Rsh[6] = 2.0f * (qa * qc - qw * qb);
        Rsh[7] = 2.0f * (qb * qc + qw * qa);
        Rsh[8] = 1.0f - 2.0f * (qa * qa + qb * qb);
        tsh[0] = Ts[t * 7 + 4]; tsh[1] = Ts[t * 7 + 5]; tsh[2] = Ts[t * 7 + 6];
        #pragma unroll
        for (int i = 0; i < 9; i++) g_R[t * 9 + i] = Rsh[i];
    }
    __syncthreads();
    {
        int o = tid;
        float acc = b_qt[o];
        for (int k = 0; k < 128; k++) acc += te[k] * W_qt[k * TEH + o];
        qemb[o] = acc;
    }
    __syncthreads();
    {
        int s = tid >> 6, j = tid & 63;
        float acc = b1_r[s * 64 + j];
        const float* w = W1_r + s * 136 * 64 + 8 * 64 + j;
        for (int i = 0; i < 128; i++) acc += qemb[i] * w[i * 64];
        g_pre[(s * NT + t) * 64 + j] = acc;
    }
    for (int q = tid; q < NQ; q += blockDim.x) {
        float x = query_x[q * 3 + 0], y = query_x[q * 3 + 1], z = query_x[q * 3 + 2];
        int n = t * NQ + q;
        g_qx[n * 3 + 0] = Rsh[0] * x + Rsh[1] * y + Rsh[2] * z + tsh[0];
        g_qx[n * 3 + 1] = Rsh[3] * x + Rsh[4] * y + Rsh[5] * z + tsh[1];
        g_qx[n * 3 + 2] = Rsh[6] * x + Rsh[7] * y + Rsh[8] * z + tsh[2];
    }
    int gtid = t * blockDim.x + tid;
    int gst = gridDim.x * blockDim.x;
    for (int z = gtid; z < 2 * NN; z += gst)
        g_invcnt[z] = 1.0f / ((float)g_cnt[z] + 1e-8f);
}

// ---------------- fused edge kernel: mma.sync fp16, 16 warps ----------------
// 148 persistent blocks of 512 threads; even blocks scale 0, odd scale 1;
// 128-edge tiles. H[128x192] = silu(layer1)[128x64] @ W2[64x192] via single
// fp16 m16n8k16 mma (fp32 accumulate). fp16 rounding error ~5e-4/element,
// averages below 1e-4 in the final contractions. B fragments in registers.
// Warp (cg, rh): 24 cols x 64 rows. Phase 5: branch-free gather, then merge.
__global__ __launch_bounds__(NTHREADS, 1)
void edge_mma_kernel(
    const float* __restrict__ kx0, const float* __restrict__ kf0,
    const float* __restrict__ kx1, const float* __restrict__ kf1,
    const float* __restrict__ W1_r, const float* __restrict__ W2_r,
    const float* __restrict__ b2_r) {
    extern __shared__ char smem[];
    int tid = threadIdx.x;
    int wid = tid >> 5, lane = tid & 31;
    int quad = lane >> 2, lm4 = lane & 3;
    int s = blockIdx.x & 1;
    int tstart = blockIdx.x >> 1;

    const float* kx = s ? kx1 : kx0;
    const float* kf = s ? kf1 : kf0;
    const float* preS = g_pre + s * NT * 64;
    const float* icS = g_invcnt + s * NN;
    const int2* srtS = g_srt + s * NE;

    uint2*  Bf2  = (uint2*)(smem + OFF_BF);
    uint32_t* Aw = (uint32_t*)(smem + OFF_A);
    float* Hs   = (float*)(smem + OFF_HS);
    float* rbs  = (float*)(smem + OFF_RBS);
    float* dirs = (float*)(smem + OFF_DIRS);
    float* invs = (float*)(smem + OFF_INVS);
    int*   srcs = (int*)(smem + OFF_SRCS);
    int*   dsts = (int*)(smem + OFF_DSTS);
    int*   tts  = (int*)(smem + OFF_TTS);
    float* W1s  = (float*)(smem + OFF_W1S);
    float* b2s  = (float*)(smem + OFF_B2S);

    // --- prologue: W1, b2, B-fragment pack (fp16) ---
    for (int i = tid; i < 512; i += NTHREADS) W1s[i] = W1_r[s * (136 * 64) + i];
    for (int i = tid; i < 192; i += NTHREADS) b2s[i] = b2_r[s * 192 + i];
    // fragment id f = kt*24 + gn ; entry (f, lane)
    for (int idx = tid; idx < 3072; idx += NTHREADS) {
        int l = idx & 31;
        int f = idx >> 5;
        int gn = f % 24;
        int kt = f / 24;
        int n = gn * 8 + (l >> 2);
        int k0 = kt * 16 + (l & 3) * 2;
        const float* w2 = W2_r + s * 12288;
        uint32_t r0 = pack_half2(w2[k0 * 192 + n], w2[(k0 + 1) * 192 + n]);
        uint32_t r1 = pack_half2(w2[(k0 + 8) * 192 + n], w2[(k0 + 9) * 192 + n]);
        Bf2[f * 32 + l] = make_uint2(r0, r1);
    }
    __syncthreads();

    int cg = wid & 7;       // column group: cols [24cg, 24cg+24)
    int rh = wid >> 3;      // row half: rows [64rh, 64rh+64)

    // per-warp B fragments resident in registers (3 nt x 4 kt x 2 regs)
    uint32_t bfr[3][4][2];
    #pragma unroll
    for (int nt = 0; nt < 3; nt++)
        #pragma unroll
        for (int kt = 0; kt < 4; kt++) {
            int f = kt * 24 + (cg * 3 + nt);
            uint2 v = Bf2[f * 32 + lane];
            bfr[nt][kt][0] = v.x;
            bfr[nt][kt][1] = v.y;
        }

    for (int tile = tstart; tile < TILES2; tile += BPS) {
        __syncthreads();
        // phase 1: per-edge geometry + rbf (dst-sorted edges)
        if (tid < TILE_E) {
            int2 sd = srtS[tile * TILE_E + tid];
            int src = sd.x, dst = sd.y;
            float rx = kx[src * 3 + 0] - g_qx[dst * 3 + 0];
            float ry = kx[src * 3 + 1] - g_qx[dst * 3 + 1];
            float rz = kx[src * 3 + 2] - g_qx[dst * 3 + 2];
            float r = sqrtf(rx * rx + ry * ry + rz * rz);
            float ir = 1.0f / (r + 1e-8f);
            dirs[tid * 3 + 0] = rx * ir;
            dirs[tid * 3 + 1] = ry * ir;
            dirs[tid * 3 + 2] = rz * ir;
            #pragma unroll
            for (int i = 0; i < 8; i++) {
                float dcl = r - (4.0f / 7.0f) * (float)i;
                rbs[tid * 9 + i] = __expf(-dcl * dcl * 4.0f);
            }
            invs[tid] = icS[dst];
            srcs[tid] = src; dsts[tid] = dst; tts[tid] = dst >> 8;
        }
        __syncthreads();

        // phase 2: layer1 + silu -> fp16 pairs into A smem (16 j per thread)
        {
            int row = tid & 127;
            int jr = (tid >> 7) * 16;
            float rb[8];
            #pragma unroll
            for (int i = 0; i < 8; i++) rb[i] = rbs[row * 9 + i];
            const float* prow = preS + tts[row] * 64;
            uint32_t hw[8];
            #pragma unroll
            for (int p = 0; p < 8; p++) {
                float av[2];
                #pragma unroll
                for (int q = 0; q < 2; q++) {
                    int j = jr + p * 2 + q;
                    float h = __ldg(prow + j);
                    #pragma unroll
                    for (int i = 0; i < 8; i++) h += rb[i] * W1s[i * 64 + j];
                    av[q] = h * (1.0f / (1.0f + __expf(-h)));
                }
                hw[p] = pack_half2(av[0], av[1]);
            }
            uint32_t base = row * ASTR + (jr >> 1);
            #pragma unroll
            for (int p = 0; p < 8; p++) Aw[base + p] = hw[p];
        }
        __syncthreads();

        // phase 3: GEMM. warp (cg, rh): cols [24cg,24cg+24), rows [64rh,64rh+64).
        float acc[3][4][4];
        #pragma unroll
        for (int nt = 0; nt < 3; nt++)
            #pragma unroll
            for (int mc = 0; mc < 4; mc++)
                #pragma unroll
                for (int r = 0; r < 4; r++) acc[nt][mc][r] = 0.0f;

        #pragma unroll
        for (int mc = 0; mc < 4; mc++) {
            int r0 = rh * 64 + mc * 16 + quad;
            uint32_t ah[4][4];
            #pragma unroll
            for (int kt = 0; kt < 4; kt++) {
                uint32_t b0 = r0 * ASTR + kt * 8 + lm4;
                uint32_t b1 = (r0 + 8) * ASTR + kt * 8 + lm4;
                ah[kt][0] = Aw[b0];     ah[kt][1] = Aw[b1];
                ah[kt][2] = Aw[b0 + 4]; ah[kt][3] = Aw[b1 + 4];
            }
            #pragma unroll
            for (int nt = 0; nt < 3; nt++)
                #pragma unroll
                for (int kt = 0; kt < 4; kt++)
                    MMA_F16(acc[nt][mc], ah[kt], bfr[nt][kt]);
        }

        // phase 4: accumulators (+bias) -> Hs slab
        #pragma unroll
        for (int nt = 0; nt < 3; nt++) {
            int col = cg * 24 + nt * 8 + lm4 * 2;
            float bb0 = b2s[col], bb1 = b2s[col + 1];
            #pragma unroll
            for (int mc = 0; mc < 4; mc++) {
                int row = rh * 64 + mc * 16 + quad;
                float2 v0 = make_float2(acc[nt][mc][0] + bb0, acc[nt][mc][1] + bb1);
                float2 v1 = make_float2(acc[nt][mc][2] + bb0, acc[nt][mc][3] + bb1);
                *(float2*)&Hs[row * HSTR + col] = v0;
                *(float2*)&Hs[(row + 8) * HSTR + col] = v1;
            }
        }
        __syncthreads();

        // phase 5: branch-free gather, then message + run-merged atomic scatter.
        // warp wid: edges [8w, 8w+8)
        {
            int tx = lane;
            float kb0[8], kb1[8], kb2[8], kb3[8], kb4[8];
            #pragma unroll
            for (int e8 = 0; e8 < 8; e8++) {
                int r = wid * 8 + e8;
                const float* kfr = kf + (size_t)srcs[r] * FF;
                kb0[e8] = __ldg(kfr + tx);
                kb1[e8] = __ldg(kfr + 32 + tx);
                kb2[e8] = __ldg(kfr + 64 + 3 * tx + 0);
                kb3[e8] = __ldg(kfr + 64 + 3 * tx + 1);
                kb4[e8] = __ldg(kfr + 64 + 3 * tx + 2);
            }
            float a0 = 0.f, a1 = 0.f, a2 = 0.f, a3 = 0.f, a4 = 0.f;
            float curinv = 0.f;
            int cur = -1;
            #pragma unroll
            for (int e8 = 0; e8 < 8; e8++) {
                int r = wid * 8 + e8;
                float w0 = Hs[r * HSTR + tx];
                float w1 = Hs[r * HSTR + 32 + tx];
                float w2 = Hs[r * HSTR + 64 + tx];
                float w3 = Hs[r * HSTR + 96 + tx];
                float w4 = Hs[r * HSTR + 128 + tx];
                float w5 = Hs[r * HSTR + 160 + tx];
                float ks1 = kb0[e8], ks2 = kb1[e8];
                float kvx = kb2[e8], kvy = kb3[e8], kvz = kb4[e8];
                float dx = dirs[r * 3 + 0], dy = dirs[r * 3 + 1], dz = dirs[r * 3 + 2];
                float dot = kvx * dx + kvy * dy + kvz * dz;
                float fs1 = w0 * ks1 + w4 * dot;
                float fs2 = w1 * ks2;
                float t1 = w3 * ks1;
                float fvx = w2 * kvx + t1 * dx + w5 * (kvy * dz - kvz * dy);
                float fvy = w2 * kvy + t1 * dy + w5 * (kvz * dx - kvx * dz);
                float fvz = w2 * kvz + t1 * dz + w5 * (kvx * dy - kvy * dx);
                int dst = dsts[r];
                if (dst != cur) {
                    if (cur >= 0) {
                        float* p = g_kfeat + (size_t)cur * FF;
                        atomicAdd(p + tx, a0 * curinv);
                        atomicAdd(p + 32 + tx, a1 * curinv);
                        atomicAdd(p + 64 + 3 * tx + 0, a2 * curinv);
                        atomicAdd(p + 64 + 3 * tx + 1, a3 * curinv);
                        atomicAdd(p + 64 + 3 * tx + 2, a4 * curinv);
                    }
                    cur = dst; curinv = invs[r];
                    a0 = fs1; a1 = fs2; a2 = fvx; a3 = fvy; a4 = fvz;
                } else {
                    a0 += fs1; a1 += fs2; a2 += fvx; a3 += fvy; a4 += fvz;
                }
            }
            if (cur >= 0) {
                float* p = g_kfeat + (size_t)cur * FF;
                atomicAdd(p + tx, a0 * curinv);
                atomicAdd(p + 32 + tx, a1 * curinv);
                atomicAdd(p + 64 + 3 * tx + 0, a2 * curinv);
                atomicAdd(p + 64 + 3 * tx + 1, a3 * curinv);
                atomicAdd(p + 64 + 3 * tx + 2, a4 * curinv);
            }
        }
    }
}

// ---------------- tensor-product heads + final reduction ----------------
__global__ __launch_bounds__(256) void tp_kernel(
    const float* __restrict__ query_f, const float* __restrict__ query_x,
    const float* __restrict__ query_w,
    const float* __restrict__ p00, const float* __restrict__ prest,
    const float* __restrict__ Ws_tp, const float* __restrict__ Wv_tp,
    float* __restrict__ out) {
    __shared__ float Wss[96 * 33];
    __shared__ float Wvs[96 * 32];
    __shared__ float s_sh[8][96];
    __shared__ float v_sh[8][96 * 3];
    __shared__ float accOut[6];
    int tid = threadIdx.x;
    int w = tid >> 5, c = tid & 31;
    int n = blockIdx.x * 8 + w;
    int t = n >> 8, q = n & 255;
    if (tid < 6) accOut[tid] = 0.0f;

    const float* kfr = g_kfeat + (size_t)n * FF;
    const float* qfr = query_f + (size_t)q * FF;
    float ks1 = kfr[c], ks2 = kfr[32 + c];
    float kvx = kfr[64 + 3 * c + 0], kvy = kfr[64 + 3 * c + 1], kvz = kfr[64 + 3 * c + 2];
    float qs1 = qfr[c], qs2 = qfr[32 + c];
    float qrx = qfr[64 + 3 * c + 0], qry = qfr[64 + 3 * c + 1], qrz = qfr[64 + 3 * c + 2];
    float R[9];
    #pragma unroll
    for (int i = 0; i < 9; i++) R[i] = __ldg(g_R + t * 9 + i);
    float qvx = R[0] * qrx + R[1] * qry + R[2] * qrz;
    float qvy = R[3] * qrx + R[4] * qry + R[5] * qrz;
    float qvz = R[6] * qrx + R[7] * qry + R[8] * qrz;

    float lin[3], ang[3];
    for (int head = 0; head < 2; head++) {
        __syncthreads();
        for (int i = tid; i < 96 * 33; i += 256) Wss[i] = Ws_tp[head * (96 * 33) + i];
        for (int i = tid; i < 96 * 32; i += 256) Wvs[i] = Wv_tp[head * (96 * 32) + i];
        __syncthreads();
        float p1 = __ldg(p00 + head * 64 + c);
        float p2 = __ldg(p00 + head * 64 + 32 + c);
        float pr0 = __ldg(prest + head * 128 + c);
        float pr1 = __ldg(prest + head * 128 + 32 + c);
        float pr2 = __ldg(prest + head * 128 + 64 + c);
        float pr3 = __ldg(prest + head * 128 + 96 + c);
        s_sh[w][c] = p1 * ks1 * qs1;
        s_sh[w][32 + c] = p2 * ks2 * qs2;
        s_sh[w][64 + c] = pr2 * (kvx * qvx + kvy * qvy + kvz * qvz);
        v_sh[w][3 * c + 0] = pr0 * kvx * qs1;
        v_sh[w][3 * c + 1] = pr0 * kvy * qs1;
        v_sh[w][3 * c + 2] = pr0 * kvz * qs1;
        v_sh[w][3 * (32 + c) + 0] = pr1 * ks1 * qvx;
        v_sh[w][3 * (32 + c) + 1] = pr1 * ks1 * qvy;
        v_sh[w][3 * (32 + c) + 2] = pr1 * ks1 * qvz;
        v_sh[w][3 * (64 + c) + 0] = pr3 * (kvy * qvz - kvz * qvy);
        v_sh[w][3 * (64 + c) + 1] = pr3 * (kvz * qvx - kvx * qvz);
        v_sh[w][3 * (64 + c) + 2] = pr3 * (kvx * qvy - kvy * qvx);
        __syncwarp();
        float sg = 0.0f, vmx = 0.0f, vmy = 0.0f, vmz = 0.0f;
        #pragma unroll 4
        for (int ch = 0; ch < 96; ch++) {
            float sv = s_sh[w][ch];
            sg += sv * Wss[ch * 33 + 1 + c];
            float wv = Wvs[ch * 32 + c];
            vmx += v_sh[w][3 * ch + 0] * wv;
            vmy += v_sh[w][3 * ch + 1] * wv;
            vmz += v_sh[w][3 * ch + 2] * wv;
        }
        float sig = 1.0f / (1.0f + __expf(-sg));
        float px = vmx * sig, py = vmy * sig, pz = vmz * sig;
        #pragma unroll
        for (int off = 16; off > 0; off >>= 1) {
            px += __shfl_xor_sync(0xffffffffu, px, off);
            py += __shfl_xor_sync(0xffffffffu, py, off);
            pz += __shfl_xor_sync(0xffffffffu, pz, off);
        }
        float sc = 1.0f / 32.0f;
        if (head == 0) { lin[0] = px * sc; lin[1] = py * sc; lin[2] = pz * sc; }
        else { ang[0] = px * sc; ang[1] = py * sc; ang[2] = pz * sc; }
        __syncwarp();
    }
    __syncthreads();
    if (c == 0) {
        float lwx = R[0] * lin[0] + R[3] * lin[1] + R[6] * lin[2];
        float lwy = R[1] * lin[0] + R[4] * lin[1] + R[7] * lin[2];
        float lwz = R[2] * lin[0] + R[5] * lin[1] + R[8] * lin[2];
        float awx = R[0] * ang[0] + R[3] * ang[1] + R[6] * ang[2];
        float awy = R[1] * ang[0] + R[4] * ang[1] + R[7] * ang[2];
        float awz = R[2] * ang[0] + R[5] * ang[1] + R[8] * ang[2];
        float qx0 = query_x[q * 3 + 0], qx1 = query_x[q * 3 + 1], qx2 = query_x[q * 3 + 2];
        float ox = qx1 * lwz - qx2 * lwy;
        float oy = qx2 * lwx - qx0 * lwz;
        float oz = qx0 * lwy - qx1 * lwx;
        float ww = query_w[q];
        atomicAdd(&accOut[0], ww * (ox + awx));
        atomicAdd(&accOut[1], ww * (oy + awy));
        atomicAdd(&accOut[2], ww * (oz + awz));
        atomicAdd(&accOut[3], ww * lwx);
        atomicAdd(&accOut[4], ww * lwy);
        atomicAdd(&accOut[5], ww * lwz);
    }
    __syncthreads();
    if (tid < 6) {
        int tt = blockIdx.x >> 5;
        int idx = (tid < 3) ? (tt * 3 + tid) : (NT * 3 + tt * 3 + (tid - 3));
        atomicAdd(out + idx, accOut[tid]);
    }
}

extern "C" void kernel_launch(void* const* d_in, const int* in_sizes, int n_in,
                              void* d_out, int out_size) {
    const float* Ts      = (const float*)d_in[0];
    const float* time_   = (const float*)d_in[1];
    const float* query_x = (const float*)d_in[2];
    const float* query_f = (const float*)d_in[3];
    const float* query_w = (const float*)d_in[4];
    const float* kx0     = (const float*)d_in[5];
    const float* kf0     = (const float*)d_in[6];
    const float* kx1     = (const float*)d_in[7];
    const float* kf1     = (const float*)d_in[8];
    const int*   es0     = (const int*)d_in[9];
    const int*   ed0     = (const int*)d_in[10];
    const int*   es1     = (const int*)d_in[11];
    const int*   ed1     = (const int*)d_in[12];
    const float* W_qt    = (const float*)d_in[13];
    const float* b_qt    = (const float*)d_in[14];
    const float* W1_r    = (const float*)d_in[15];
    const float* b1_r    = (const float*)d_in[16];
    const float* W2_r    = (const float*)d_in[17];
    const float* b2_r    = (const float*)d_in[18];
    const float* p00     = (const float*)d_in[19];
    const float* prest   = (const float*)d_in[20];
    const float* Ws_tp   = (const float*)d_in[21];
    const float* Wv_tp   = (const float*)d_in[22];
    float* out = (float*)d_out;

    cudaFuncSetAttribute(edge_mma_kernel, cudaFuncAttributeMaxDynamicSharedMemorySize,
                         EDGE_SMEM);

    zero_kernel<<<2048, 256>>>(out);
    hist_kernel<<<1024, 256>>>(ed0, ed1);
    scan_kernel<<<1, 1024>>>();
    prep_kernel<<<NT, 128>>>(Ts, time_, query_x, W_qt, b_qt, W1_r, b1_r);
    scatter_kernel<<<512, 256>>>(es0, ed0, es1, ed1);
    edge_mma_kernel<<<148, NTHREADS, EDGE_SMEM>>>(kx0, kf0, kx1, kf1, W1_r, W2_r, b2_r);
    tp_kernel<<<NN / 8, 256>>>(query_f, query_x, query_w, p00, prest, Ws_tp, Wv_tp, out);
}

// round 9
// speedup vs baseline: 1.7231x; 1.0405x over previous
#include <cuda_runtime.h>
#include <cuda_bf16.h>
#include <cuda_fp16.h>
#include <math.h>
#include <stdint.h>

#define NT 64
#define NQ 256
#define NPK 100000
#define NE 262144
#define NN 16384
#define DS 64
#define DV 32
#define TEH 128
#define FF 160

#define TILE_E 64
#define TILES4 4096          // tiles per scale (NE / 64)
#define BPS 148              // blocks per scale (296 total)
#define HSTR 196             // Hs row stride (floats)
#define ASTR 37              // A row stride (32-bit words)
#define NTHREADS 256

// smem byte offsets (91136 B total -> 2 CTAs/SM)
#define OFF_BF   0           // B fragments: 96 frags x 32 lanes x 8 B = 24576
#define OFF_A    24576       // 64 x 37 words = 9472
#define OFF_HS   34048       // 64 x 196 floats = 50176
#define OFF_RBS  84224       // 64 x 9 floats = 2304
#define OFF_DIRS 86528       // 768
#define OFF_INVS 87296       // 256
#define OFF_SRCS 87552       // 256
#define OFF_DSTS 87808       // 256
#define OFF_TTS  88064       // 256
#define OFF_W1S  88320       // 2048
#define OFF_B2S  90368       // 768
#define EDGE_SMEM 91136

__device__ float g_kfeat[NN * FF];
__device__ int   g_cnt[2 * NN];
__device__ int   g_cur[2 * NN];
__device__ float g_invcnt[2 * NN];
__device__ float g_qx[NN * 3];
__device__ float g_R[NT * 9];
__device__ float g_pre[2 * NT * 64];
__device__ int2  g_srt[2 * NE];

__device__ __forceinline__ uint32_t pack_half2(float a, float b) {
    __half2 h = __floats2half2_rn(a, b);
    return *reinterpret_cast<uint32_t*>(&h);
}

#define MMA_F16(c, a, b) \
    asm volatile("mma.sync.aligned.m16n8k16.row.col.f32.f16.f16.f32 " \
        "{%0,%1,%2,%3}, {%4,%5,%6,%7}, {%8,%9}, {%0,%1,%2,%3};" \
        : "+f"((c)[0]), "+f"((c)[1]), "+f"((c)[2]), "+f"((c)[3]) \
        : "r"((a)[0]), "r"((a)[1]), "r"((a)[2]), "r"((a)[3]), \
          "r"((b)[0]), "r"((b)[1]))

// ---------------- small kernels ----------------
__global__ void zero_kernel(float* __restrict__ out) {
    int i = blockIdx.x * blockDim.x + threadIdx.x;
    int st = gridDim.x * blockDim.x;
    for (int z = i; z < NN * FF; z += st) g_kfeat[z] = 0.0f;
    for (int z = i; z < 2 * NN; z += st) g_cnt[z] = 0;
    if (i < 2 * NT * 3) out[i] = 0.0f;
}

__global__ void hist_kernel(const int* __restrict__ ed0, const int* __restrict__ ed1) {
    int i = blockIdx.x * blockDim.x + threadIdx.x;
    int st = gridDim.x * blockDim.x;
    for (int e = i; e < NE; e += st) atomicAdd(&g_cnt[ed0[e]], 1);
    for (int e = i; e < NE; e += st) atomicAdd(&g_cnt[NN + ed1[e]], 1);
}

__global__ void scan_kernel() {
    __shared__ int sm[1024];
    int tid = threadIdx.x;
    int base = tid * 32;
    int loc[32];
    int s = 0;
    #pragma unroll
    for (int i = 0; i < 32; i++) { loc[i] = g_cnt[base + i]; s += loc[i]; }
    sm[tid] = s;
    __syncthreads();
    for (int off = 1; off < 1024; off <<= 1) {
        int v = (tid >= off) ? sm[tid - off] : 0;
        __syncthreads();
        sm[tid] += v;
        __syncthreads();
    }
    int ex = sm[tid] - s;
    #pragma unroll
    for (int i = 0; i < 32; i++) { g_cur[base + i] = ex; ex += loc[i]; }
}

__global__ void scatter_kernel(const int* __restrict__ es0, const int* __restrict__ ed0,
                               const int* __restrict__ es1, const int* __restrict__ ed1) {
    int i = blockIdx.x * blockDim.x + threadIdx.x;
    int st = gridDim.x * blockDim.x;
    for (int e = i; e < NE; e += st) {
        int d = ed0[e];
        int pos = atomicAdd(&g_cur[d], 1);
        g_srt[pos] = make_int2(es0[e], d);
    }
    for (int e = i; e < NE; e += st) {
        int d = ed1[e];
        int pos = atomicAdd(&g_cur[NN + d], 1);
        g_srt[pos] = make_int2(es1[e], d);
    }
}

__global__ void prep_kernel(const float* __restrict__ Ts, const float* __restrict__ time_,
                            const float* __restrict__ query_x,
                            const float* __restrict__ W_qt, const float* __restrict__ b_qt,
                            const float* __restrict__ W1_r, const float* __restrict__ b1_r) {
    __shared__ float te[128];
    __shared__ float qemb[128];
    __shared__ float Rsh[9];
    __shared__ float tsh[3];
    int t = blockIdx.x;
    int tid = threadIdx.x;  // 128 threads
    float tv = time_[t];
    {
        int k = tid & 63;
        float f = __expf(-logf(10000.0f) * (float)k / 63.0f);
        float a = tv * f;
        te[tid] = (tid < 64) ? sinf(a) : cosf(a);
    }
    if (tid == 0) {
        float qw = Ts[t * 7 + 0], qa = Ts[t * 7 + 1], qb = Ts[t * 7 + 2], qc = Ts[t * 7 + 3];
        float nrm = rsqrtf(qw * qw + qa * qa + qb * qb + qc * qc);
        qw *= nrm; qa *= nrm; qb *= nrm; qc *= nrm;
        Rsh[0] = 1.0f - 2.0f * (qb * qb + qc * qc);
        Rsh[1] = 2.0f * (qa * qb - qw * qc);
        Rsh[2] = 2.0f * (qa * qc + qw * qb);
        Rsh[3] = 2.0f * (qa * qb + qw * qc);
        Rsh[4] = 1.0f - 2.0f * (qa * qa + qc * qc);
        Rsh[5] = 2.0f * (qb * qc - qw * qa);
        Rsh[6] = 2.0f * (qa * qc - qw * qb);
        Rsh[7] = 2.0f * (qb * qc + qw * qa);
        Rsh[8] = 1.0f - 2.0f * (qa * qa + qb * qb);
        tsh[0] = Ts[t * 7 + 4]; tsh[1] = Ts[t * 7 + 5]; tsh[2] = Ts[t * 7 + 6];
        #pragma unroll
        for (int i = 0; i < 9; i++) g_R[t * 9 + i] = Rsh[i];
    }
    __syncthreads();
    {
        int o = tid;
        float acc = b_qt[o];
        for (int k = 0; k < 128; k++) acc += te[k] * W_qt[k * TEH + o];
        qemb[o] = acc;
    }
    __syncthreads();
    {
        int s = tid >> 6, j = tid & 63;
        float acc = b1_r[s * 64 + j];
        const float* w = W1_r + s * 136 * 64 + 8 * 64 + j;
        for (int i = 0; i < 128; i++) acc += qemb[i] * w[i * 64];
        g_pre[(s * NT + t) * 64 + j] = acc;
    }
    for (int q = tid; q < NQ; q += blockDim.x) {
        float x = query_x[q * 3 + 0], y = query_x[q * 3 + 1], z = query_x[q * 3 + 2];
        int n = t * NQ + q;
        g_qx[n * 3 + 0] = Rsh[0] * x + Rsh[1] * y + Rsh[2] * z + tsh[0];
        g_qx[n * 3 + 1] = Rsh[3] * x + Rsh[4] * y + Rsh[5] * z + tsh[1];
        g_qx[n * 3 + 2] = Rsh[6] * x + Rsh[7] * y + Rsh[8] * z + tsh[2];
    }
    int gtid = t * blockDim.x + tid;
    int gst = gridDim.x * blockDim.x;
    for (int z = gtid; z < 2 * NN; z += gst)
        g_invcnt[z] = 1.0f / ((float)g_cnt[z] + 1e-8f);
}

// ---------------- fused edge kernel: mma.sync fp16, 2 CTAs/SM ----------------
// 296 blocks of 256 threads (2 per SM); even blocks scale 0, odd scale 1;
// 64-edge tiles. H[64x192] = silu(layer1)[64x64] @ W2[64x192] via fp16
// m16n8k16 mma (fp32 accumulate). Two co-resident CTAs per SM hide each
// other's gather/atomic/barrier latency. Warp cg: 24 cols x 64 rows.
__global__ __launch_bounds__(NTHREADS, 2)
void edge_mma_kernel(
    const float* __restrict__ kx0, const float* __restrict__ kf0,
    const float* __restrict__ kx1, const float* __restrict__ kf1,
    const float* __restrict__ W1_r, const float* __restrict__ W2_r,
    const float* __restrict__ b2_r) {
    extern __shared__ char smem[];
    int tid = threadIdx.x;
    int wid = tid >> 5, lane = tid & 31;
    int quad = lane >> 2, lm4 = lane & 3;
    int s = blockIdx.x & 1;
    int tstart = blockIdx.x >> 1;

    const float* kx = s ? kx1 : kx0;
    const float* kf = s ? kf1 : kf0;
    const float* preS = g_pre + s * NT * 64;
    const float* icS = g_invcnt + s * NN;
    const int2* srtS = g_srt + s * NE;

    uint2*  Bf2  = (uint2*)(smem + OFF_BF);
    uint32_t* Aw = (uint32_t*)(smem + OFF_A);
    float* Hs   = (float*)(smem + OFF_HS);
    float* rbs  = (float*)(smem + OFF_RBS);
    float* dirs = (float*)(smem + OFF_DIRS);
    float* invs = (float*)(smem + OFF_INVS);
    int*   srcs = (int*)(smem + OFF_SRCS);
    int*   dsts = (int*)(smem + OFF_DSTS);
    int*   tts  = (int*)(smem + OFF_TTS);
    float* W1s  = (float*)(smem + OFF_W1S);
    float* b2s  = (float*)(smem + OFF_B2S);

    // --- prologue: W1, b2, B-fragment pack (fp16) ---
    for (int i = tid; i < 512; i += NTHREADS) W1s[i] = W1_r[s * (136 * 64) + i];
    for (int i = tid; i < 192; i += NTHREADS) b2s[i] = b2_r[s * 192 + i];
    // fragment id f = kt*24 + gn ; entry (f, lane)
    for (int idx = tid; idx < 3072; idx += NTHREADS) {
        int l = idx & 31;
        int f = idx >> 5;
        int gn = f % 24;
        int kt = f / 24;
        int n = gn * 8 + (l >> 2);
        int k0 = kt * 16 + (l & 3) * 2;
        const float* w2 = W2_r + s * 12288;
        uint32_t r0 = pack_half2(w2[k0 * 192 + n], w2[(k0 + 1) * 192 + n]);
        uint32_t r1 = pack_half2(w2[(k0 + 8) * 192 + n], w2[(k0 + 9) * 192 + n]);
        Bf2[f * 32 + l] = make_uint2(r0, r1);
    }
    __syncthreads();

    int cg = wid;           // column group: cols [24cg, 24cg+24)

    // per-warp B fragments resident in registers (3 nt x 4 kt x 2 regs)
    uint32_t bfr[3][4][2];
    #pragma unroll
    for (int nt = 0; nt < 3; nt++)
        #pragma unroll
        for (int kt = 0; kt < 4; kt++) {
            int f = kt * 24 + (cg * 3 + nt);
            uint2 v = Bf2[f * 32 + lane];
            bfr[nt][kt][0] = v.x;
            bfr[nt][kt][1] = v.y;
        }

    for (int tile = tstart; tile < TILES4; tile += BPS) {
        __syncthreads();
        // phase 1: per-edge geometry + rbf (dst-sorted edges)
        if (tid < TILE_E) {
            int2 sd = srtS[tile * TILE_E + tid];
            int src = sd.x, dst = sd.y;
            float rx = kx[src * 3 + 0] - g_qx[dst * 3 + 0];
            float ry = kx[src * 3 + 1] - g_qx[dst * 3 + 1];
            float rz = kx[src * 3 + 2] - g_qx[dst * 3 + 2];
            float r = sqrtf(rx * rx + ry * ry + rz * rz);
            float ir = 1.0f / (r + 1e-8f);
            dirs[tid * 3 + 0] = rx * ir;
            dirs[tid * 3 + 1] = ry * ir;
            dirs[tid * 3 + 2] = rz * ir;
            #pragma unroll
            for (int i = 0; i < 8; i++) {
                float dcl = r - (4.0f / 7.0f) * (float)i;
                rbs[tid * 9 + i] = __expf(-dcl * dcl * 4.0f);
            }
            invs[tid] = icS[dst];
            srcs[tid] = src; dsts[tid] = dst; tts[tid] = dst >> 8;
        }
        __syncthreads();

        // phase 2: layer1 + silu -> fp16 pairs into A smem (16 j per thread)
        {
            int row = tid & 63;
            int jr = (tid >> 6) * 16;
            float rb[8];
            #pragma unroll
            for (int i = 0; i < 8; i++) rb[i] = rbs[row * 9 + i];
            const float* prow = preS + tts[row] * 64;
            uint32_t hw[8];
            #pragma unroll
            for (int p = 0; p < 8; p++) {
                float av[2];
                #pragma unroll
                for (int q = 0; q < 2; q++) {
                    int j = jr + p * 2 + q;
                    float h = __ldg(prow + j);
                    #pragma unroll
                    for (int i = 0; i < 8; i++) h += rb[i] * W1s[i * 64 + j];
                    av[q] = h * (1.0f / (1.0f + __expf(-h)));
                }
                hw[p] = pack_half2(av[0], av[1]);
            }
            uint32_t base = row * ASTR + (jr >> 1);
            #pragma unroll
            for (int p = 0; p < 8; p++) Aw[base + p] = hw[p];
        }
        __syncthreads();

        // phase 3: GEMM. warp cg: cols [24cg,24cg+24), rows 0..63.
        float acc[3][4][4];
        #pragma unroll
        for (int nt = 0; nt < 3; nt++)
            #pragma unroll
            for (int mc = 0; mc < 4; mc++)
                #pragma unroll
                for (int r = 0; r < 4; r++) acc[nt][mc][r] = 0.0f;

        #pragma unroll
        for (int mc = 0; mc < 4; mc++) {
            int r0 = mc * 16 + quad;
            uint32_t ah[4][4];
            #pragma unroll
            for (int kt = 0; kt < 4; kt++) {
                uint32_t b0 = r0 * ASTR + kt * 8 + lm4;
                uint32_t b1 = (r0 + 8) * ASTR + kt * 8 + lm4;
                ah[kt][0] = Aw[b0];     ah[kt][1] = Aw[b1];
                ah[kt][2] = Aw[b0 + 4]; ah[kt][3] = Aw[b1 + 4];
            }
            #pragma unroll
            for (int nt = 0; nt < 3; nt++)
                #pragma unroll
                for (int kt = 0; kt < 4; kt++)
                    MMA_F16(acc[nt][mc], ah[kt], bfr[nt][kt]);
        }

        // phase 4: accumulators (+bias) -> Hs slab
        #pragma unroll
        for (int nt = 0; nt < 3; nt++) {
            int col = cg * 24 + nt * 8 + lm4 * 2;
            float bb0 = b2s[col], bb1 = b2s[col + 1];
            #pragma unroll
            for (int mc = 0; mc < 4; mc++) {
                int row = mc * 16 + quad;
                float2 v0 = make_float2(acc[nt][mc][0] + bb0, acc[nt][mc][1] + bb1);
                float2 v1 = make_float2(acc[nt][mc][2] + bb0, acc[nt][mc][3] + bb1);
                *(float2*)&Hs[row * HSTR + col] = v0;
                *(float2*)&Hs[(row + 8) * HSTR + col] = v1;
            }
        }
        __syncthreads();

        // phase 5: branch-free gather, then message + run-merged atomic scatter.
        // warp wid: edges [8w, 8w+8)
        {
            int tx = lane;
            float kb0[8], kb1[8], kb2[8], kb3[8], kb4[8];
            #pragma unroll
            for (int e8 = 0; e8 < 8; e8++) {
                int r = wid * 8 + e8;
                const float* kfr = kf + (size_t)srcs[r] * FF;
                kb0[e8] = __ldg(kfr + tx);
                kb1[e8] = __ldg(kfr + 32 + tx);
                kb2[e8] = __ldg(kfr + 64 + 3 * tx + 0);
                kb3[e8] = __ldg(kfr + 64 + 3 * tx + 1);
                kb4[e8] = __ldg(kfr + 64 + 3 * tx + 2);
            }
            float a0 = 0.f, a1 = 0.f, a2 = 0.f, a3 = 0.f, a4 = 0.f;
            float curinv = 0.f;
            int cur = -1;
            #pragma unroll
            for (int e8 = 0; e8 < 8; e8++) {
                int r = wid * 8 + e8;
                float w0 = Hs[r * HSTR + tx];
                float w1 = Hs[r * HSTR + 32 + tx];
                float w2 = Hs[r * HSTR + 64 + tx];
                float w3 = Hs[r * HSTR + 96 + tx];
                float w4 = Hs[r * HSTR + 128 + tx];
                float w5 = Hs[r * HSTR + 160 + tx];
                float ks1 = kb0[e8], ks2 = kb1[e8];
                float kvx = kb2[e8], kvy = kb3[e8], kvz = kb4[e8];
                float dx = dirs[r * 3 + 0], dy = dirs[r * 3 + 1], dz = dirs[r * 3 + 2];
                float dot = kvx * dx + kvy * dy + kvz * dz;
                float fs1 = w0 * ks1 + w4 * dot;
                float fs2 = w1 * ks2;
                float t1 = w3 * ks1;
                float fvx = w2 * kvx + t1 * dx + w5 * (kvy * dz - kvz * dy);
                float fvy = w2 * kvy + t1 * dy + w5 * (kvz * dx - kvx * dz);
                float fvz = w2 * kvz + t1 * dz + w5 * (kvx * dy - kvy * dx);
                int dst = dsts[r];
                if (dst != cur) {
                    if (cur >= 0) {
                        float* p = g_kfeat + (size_t)cur * FF;
                        atomicAdd(p + tx, a0 * curinv);
                        atomicAdd(p + 32 + tx, a1 * curinv);
                        atomicAdd(p + 64 + 3 * tx + 0, a2 * curinv);
                        atomicAdd(p + 64 + 3 * tx + 1, a3 * curinv);
                        atomicAdd(p + 64 + 3 * tx + 2, a4 * curinv);
                    }
                    cur = dst; curinv = invs[r];
                    a0 = fs1; a1 = fs2; a2 = fvx; a3 = fvy; a4 = fvz;
                } else {
                    a0 += fs1; a1 += fs2; a2 += fvx; a3 += fvy; a4 += fvz;
                }
            }
            if (cur >= 0) {
                float* p = g_kfeat + (size_t)cur * FF;
                atomicAdd(p + tx, a0 * curinv);
                atomicAdd(p + 32 + tx, a1 * curinv);
                atomicAdd(p + 64 + 3 * tx + 0, a2 * curinv);
                atomicAdd(p + 64 + 3 * tx + 1, a3 * curinv);
                atomicAdd(p + 64 + 3 * tx + 2, a4 * curinv);
            }
        }
    }
}

// ---------------- tensor-product heads + final reduction ----------------
__global__ __launch_bounds__(256) void tp_kernel(
    const float* __restrict__ query_f, const float* __restrict__ query_x,
    const float* __restrict__ query_w,
    const float* __restrict__ p00, const float* __restrict__ prest,
    const float* __restrict__ Ws_tp, const float* __restrict__ Wv_tp,
    float* __restrict__ out) {
    __shared__ float Wss[96 * 33];
    __shared__ float Wvs[96 * 32];
    __shared__ float s_sh[8][96];
    __shared__ float v_sh[8][96 * 3];
    __shared__ float accOut[6];
    int tid = threadIdx.x;
    int w = tid >> 5, c = tid & 31;
    int n = blockIdx.x * 8 + w;
    int t = n >> 8, q = n & 255;
    if (tid < 6) accOut[tid] = 0.0f;

    const float* kfr = g_kfeat + (size_t)n * FF;
    const float* qfr = query_f + (size_t)q * FF;
    float ks1 = kfr[c], ks2 = kfr[32 + c];
    float kvx = kfr[64 + 3 * c + 0], kvy = kfr[64 + 3 * c + 1], kvz = kfr[64 + 3 * c + 2];
    float qs1 = qfr[c], qs2 = qfr[32 + c];
    float qrx = qfr[64 + 3 * c + 0], qry = qfr[64 + 3 * c + 1], qrz = qfr[64 + 3 * c + 2];
    float R[9];
    #pragma unroll
    for (int i = 0; i < 9; i++) R[i] = __ldg(g_R + t * 9 + i);
    float qvx = R[0] * qrx + R[1] * qry + R[2] * qrz;
    float qvy = R[3] * qrx + R[4] * qry + R[5] * qrz;
    float qvz = R[6] * qrx + R[7] * qry + R[8] * qrz;

    float lin[3], ang[3];
    for (int head = 0; head < 2; head++) {
        __syncthreads();
        for (int i = tid; i < 96 * 33; i += 256) Wss[i] = Ws_tp[head * (96 * 33) + i];
        for (int i = tid; i < 96 * 32; i += 256) Wvs[i] = Wv_tp[head * (96 * 32) + i];
        __syncthreads();
        float p1 = __ldg(p00 + head * 64 + c);
        float p2 = __ldg(p00 + head * 64 + 32 + c);
        float pr0 = __ldg(prest + head * 128 + c);
        float pr1 = __ldg(prest + head * 128 + 32 + c);
        float pr2 = __ldg(prest + head * 128 + 64 + c);
        float pr3 = __ldg(prest + head * 128 + 96 + c);
        s_sh[w][c] = p1 * ks1 * qs1;
        s_sh[w][32 + c] = p2 * ks2 * qs2;
        s_sh[w][64 + c] = pr2 * (kvx * qvx + kvy * qvy + kvz * qvz);
        v_sh[w][3 * c + 0] = pr0 * kvx * qs1;
        v_sh[w][3 * c + 1] = pr0 * kvy * qs1;
        v_sh[w][3 * c + 2] = pr0 * kvz * qs1;
        v_sh[w][3 * (32 + c) + 0] = pr1 * ks1 * qvx;
        v_sh[w][3 * (32 + c) + 1] = pr1 * ks1 * qvy;
        v_sh[w][3 * (32 + c) + 2] = pr1 * ks1 * qvz;
        v_sh[w][3 * (64 + c) + 0] = pr3 * (kvy * qvz - kvz * qvy);
        v_sh[w][3 * (64 + c) + 1] = pr3 * (kvz * qvx - kvx * qvz);
        v_sh[w][3 * (64 + c) + 2] = pr3 * (kvx * qvy - kvy * qvx);
        __syncwarp();
        float sg = 0.0f, vmx = 0.0f, vmy = 0.0f, vmz = 0.0f;
        #pragma unroll 4
        for (int ch = 0; ch < 96; ch++) {
            float sv = s_sh[w][ch];
            sg += sv * Wss[ch * 33 + 1 + c];
            float wv = Wvs[ch * 32 + c];
            vmx += v_sh[w][3 * ch + 0] * wv;
            vmy += v_sh[w][3 * ch + 1] * wv;
            vmz += v_sh[w][3 * ch + 2] * wv;
        }
        float sig = 1.0f / (1.0f + __expf(-sg));
        float px = vmx * sig, py = vmy * sig, pz = vmz * sig;
        #pragma unroll
        for (int off = 16; off > 0; off >>= 1) {
            px += __shfl_xor_sync(0xffffffffu, px, off);
            py += __shfl_xor_sync(0xffffffffu, py, off);
            pz += __shfl_xor_sync(0xffffffffu, pz, off);
        }
        float sc = 1.0f / 32.0f;
        if (head == 0) { lin[0] = px * sc; lin[1] = py * sc; lin[2] = pz * sc; }
        else { ang[0] = px * sc; ang[1] = py * sc; ang[2] = pz * sc; }
        __syncwarp();
    }
    __syncthreads();
    if (c == 0) {
        float lwx = R[0] * lin[0] + R[3] * lin[1] + R[6] * lin[2];
        float lwy = R[1] * lin[0] + R[4] * lin[1] + R[7] * lin[2];
        float lwz = R[2] * lin[0] + R[5] * lin[1] + R[8] * lin[2];
        float awx = R[0] * ang[0] + R[3] * ang[1] + R[6] * ang[2];
        float awy = R[1] * ang[0] + R[4] * ang[1] + R[7] * ang[2];
        float awz = R[2] * ang[0] + R[5] * ang[1] + R[8] * ang[2];
        float qx0 = query_x[q * 3 + 0], qx1 = query_x[q * 3 + 1], qx2 = query_x[q * 3 + 2];
        float ox = qx1 * lwz - qx2 * lwy;
        float oy = qx2 * lwx - qx0 * lwz;
        float oz = qx0 * lwy - qx1 * lwx;
        float ww = query_w[q];
        atomicAdd(&accOut[0], ww * (ox + awx));
        atomicAdd(&accOut[1], ww * (oy + awy));
        atomicAdd(&accOut[2], ww * (oz + awz));
        atomicAdd(&accOut[3], ww * lwx);
        atomicAdd(&accOut[4], ww * lwy);
        atomicAdd(&accOut[5], ww * lwz);
    }
    __syncthreads();
    if (tid < 6) {
        int tt = blockIdx.x >> 5;
        int idx = (tid < 3) ? (tt * 3 + tid) : (NT * 3 + tt * 3 + (tid - 3));
        atomicAdd(out + idx, accOut[tid]);
    }
}

extern "C" void kernel_launch(void* const* d_in, const int* in_sizes, int n_in,
                              void* d_out, int out_size) {
    const float* Ts      = (const float*)d_in[0];
    const float* time_   = (const float*)d_in[1];
    const float* query_x = (const float*)d_in[2];
    const float* query_f = (const float*)d_in[3];
    const float* query_w = (const float*)d_in[4];
    const float* kx0     = (const float*)d_in[5];
    const float* kf0     = (const float*)d_in[6];
    const float* kx1     = (const float*)d_in[7];
    const float* kf1     = (const float*)d_in[8];
    const int*   es0     = (const int*)d_in[9];
    const int*   ed0     = (const int*)d_in[10];
    const int*   es1     = (const int*)d_in[11];
    const int*   ed1     = (const int*)d_in[12];
    const float* W_qt    = (const float*)d_in[13];
    const float* b_qt    = (const float*)d_in[14];
    const float* W1_r    = (const float*)d_in[15];
    const float* b1_r    = (const float*)d_in[16];
    const float* W2_r    = (const float*)d_in[17];
    const float* b2_r    = (const float*)d_in[18];
    const float* p00     = (const float*)d_in[19];
    const float* prest   = (const float*)d_in[20];
    const float* Ws_tp   = (const float*)d_in[21];
    const float* Wv_tp   = (const float*)d_in[22];
    float* out = (float*)d_out;

    cudaFuncSetAttribute(edge_mma_kernel, cudaFuncAttributeMaxDynamicSharedMemorySize,
                         EDGE_SMEM);

    zero_kernel<<<2048, 256>>>(out);
    hist_kernel<<<1024, 256>>>(ed0, ed1);
    scan_kernel<<<1, 1024>>>();
    prep_kernel<<<NT, 128>>>(Ts, time_, query_x, W_qt, b_qt, W1_r, b1_r);
    scatter_kernel<<<512, 256>>>(es0, ed0, es1, ed1);
    edge_mma_kernel<<<2 * BPS, NTHREADS, EDGE_SMEM>>>(kx0, kf0, kx1, kf1, W1_r, W2_r, b2_r);
    tp_kernel<<<NN / 8, 256>>>(query_f, query_x, query_w, p00, prest, Ws_tp, Wv_tp, out);
}